// round 4
// baseline (speedup 1.0000x reference)
#include <cuda_runtime.h>
#include <math.h>

// Problem constants
#define NB 4          // batch
#define KTOT 4720     // concat candidates per image (1000*4 + 720)
#define IMGSZ 320.0f
#define THR 0.025f
#define IOUTHR 0.5f

// Per-level tables
__device__ __constant__ int   c_w[5]      = {40, 20, 10, 5, 3};
__device__ __constant__ int   c_stride[5] = {8, 16, 32, 64, 128};
__device__ __constant__ int   c_keyoff[5] = {0, 128000, 160000, 168000, 170000}; // within image
__device__ __constant__ int   c_outoff[5] = {0, 1000, 2000, 3000, 4000};
__device__ __constant__ int   c_k[5]      = {1000, 1000, 1000, 1000, 720};

#define IMG_KEYS 170720

// Scratch (static device globals; no allocation in kernel_launch)
__device__ unsigned long long g_keys[NB * IMG_KEYS];
__device__ float              g_score[NB * KTOT];
__device__ int                g_label[NB * KTOT];
__device__ float4             g_box[NB * KTOT];
__device__ unsigned char      g_valid[NB * KTOT];
__device__ int                g_order[NB * KTOT];

struct Ptrs {
    const float* cls[5];
    const float* bb[5];
    const float* ct[5];
};

__device__ __forceinline__ unsigned int ordf(float f) {
    unsigned int u = __float_as_uint(f);
    return (u & 0x80000000u) ? ~u : (u | 0x80000000u);
}
__device__ __forceinline__ float unordf(unsigned int u) {
    return __uint_as_float((u & 0x80000000u) ? (u & 0x7FFFFFFFu) : ~u);
}

// XLA:CPU f32 exp (llvm_ir_runtime GenerateVF32Exp == Eigen/Cephes pexp),
// with FMA contraction as LLVM emits under the rewrite's fast-math flags.
__device__ __forceinline__ float xla_cpu_expf(float x) {
    x = fminf(x,  88.3762626647950f);
    x = fmaxf(x, -88.3762626647949f);
    float fx = floorf(__fmaf_rn(x, 1.44269504088896341f, 0.5f));
    // Cody-Waite: r = x - fx*C1 - fx*C2,  C1=0.693359375, C2=-2.12194440e-4
    float r = __fmaf_rn(fx, -0.693359375f, x);
    r = __fmaf_rn(fx, 2.12194440e-4f, r);
    float r2 = __fmul_rn(r, r);
    float y = 1.9875691500e-4f;
    y = __fmaf_rn(y, r, 1.3981999507e-3f);
    y = __fmaf_rn(y, r, 8.3334519073e-3f);
    y = __fmaf_rn(y, r, 4.1665795894e-2f);
    y = __fmaf_rn(y, r, 1.6666665459e-1f);
    y = __fmaf_rn(y, r, 5.0000001201e-1f);
    y = __fmaf_rn(y, r2, r);
    y = __fadd_rn(y, 1.0f);
    int n = (int)fx;
    float s = __int_as_float((unsigned int)(n + 127) << 23);
    return __fmul_rn(y, s);
}
// XLA LogisticExpander: logistic(x) = 1 / (1 + exp(-x)), IEEE divide.
__device__ __forceinline__ float sigm(float x) {
    return __fdiv_rn(1.0f, __fadd_rn(1.0f, xla_cpu_expf(-x)));
}

// IoU on offset boxes, exact reference float op order, every op separately rounded.
__device__ __forceinline__ bool suppresses(const float4 a, const float4 b) {
    float aa = __fmul_rn(__fsub_rn(a.z, a.x), __fsub_rn(a.w, a.y));
    float ab = __fmul_rn(__fsub_rn(b.z, b.x), __fsub_rn(b.w, b.y));
    float ltx = fmaxf(a.x, b.x), lty = fmaxf(a.y, b.y);
    float rbx = fminf(a.z, b.z), rby = fminf(a.w, b.w);
    float w = fmaxf(__fsub_rn(rbx, ltx), 0.0f), h = fmaxf(__fsub_rn(rby, lty), 0.0f);
    float inter = __fmul_rn(w, h);
    float uni = __fsub_rn(__fadd_rn(aa, ab), inter);
    float iou = (uni > 0.0f) ? __fdiv_rn(inter, uni) : 0.0f;
    return iou > IOUTHR;
}

// ---------------------------------------------------------------------------
// Kernel 1: per (level, image) block — sigmoid scores, exact radix-select top-k,
// SMEM bitonic sort of top-k, decode + box computation, write concat arrays.
// ---------------------------------------------------------------------------
__global__ __launch_bounds__(1024) void k_topk(Ptrs p) {
    const int lvl = blockIdx.x;
    const int b = blockIdx.y;
    const int tid = threadIdx.x;

    const int w = c_w[lvl];
    const int h = w;
    const int A = w * w;
    const int N = A * 80;
    const int k = c_k[lvl];
    const int stride = c_stride[lvl];

    unsigned long long* keys = g_keys + b * IMG_KEYS + c_keyoff[lvl];
    const float* cls = p.cls[lvl];

    // Phase A: sigmoid + masked score -> unique key
    for (int e = tid; e < N; e += 1024) {
        int anchor = e / 80;
        int c = e - anchor * 80;
        int y = anchor / w;
        int x = anchor - y * w;
        float f = cls[((b * 80 + c) * h + y) * w + x];
        float s = sigm(f);
        float mv = (s > THR) ? s : -1.0f;
        unsigned int hi = ~ordf(mv);
        keys[e] = ((unsigned long long)hi << 32) | (unsigned int)e;
    }
    __syncthreads();

    // Phase B: exact radix select of k-th smallest key (keys unique)
    __shared__ unsigned int hist[256];
    __shared__ unsigned long long s_pref;
    __shared__ int s_kk;
    if (tid == 0) { s_pref = 0ull; s_kk = k; }
    __syncthreads();

    for (int r = 0; r < 8; r++) {
        for (int i = tid; i < 256; i += 1024) hist[i] = 0;
        __syncthreads();
        unsigned long long pref = s_pref;
        int shift = 56 - 8 * r;
        for (int e = tid; e < N; e += 1024) {
            unsigned long long key = keys[e];
            bool m = (r == 0) || ((key >> (shift + 8)) == (pref >> (shift + 8)));
            if (m) atomicAdd(&hist[(unsigned int)(key >> shift) & 0xFFu], 1u);
        }
        __syncthreads();
        if (tid == 0) {
            int kk = s_kk;
            unsigned int cum = 0;
            for (int bin = 0; bin < 256; bin++) {
                unsigned int c2 = hist[bin];
                if (cum + c2 >= (unsigned int)kk) {
                    s_kk = kk - (int)cum;
                    s_pref = pref | ((unsigned long long)bin << shift);
                    break;
                }
                cum += c2;
            }
        }
        __syncthreads();
    }
    unsigned long long kth = s_pref;

    // Phase C: gather exactly-k keys <= kth, pad, bitonic sort 1024 in SMEM
    __shared__ unsigned long long buf[1024];
    __shared__ int s_cnt;
    if (tid == 0) s_cnt = 0;
    __syncthreads();
    for (int e = tid; e < N; e += 1024) {
        unsigned long long key = keys[e];
        if (key <= kth) {
            int pos = atomicAdd(&s_cnt, 1);
            if (pos < 1024) buf[pos] = key;
        }
    }
    __syncthreads();
    if (tid >= s_cnt) buf[tid] = ~0ull;
    __syncthreads();

    for (int ks2 = 2; ks2 <= 1024; ks2 <<= 1) {
        for (int j = ks2 >> 1; j > 0; j >>= 1) {
            int ixj = tid ^ j;
            if (ixj > tid) {
                unsigned long long a = buf[tid], bv = buf[ixj];
                if ((a > bv) == ((tid & ks2) == 0)) { buf[tid] = bv; buf[ixj] = a; }
            }
            __syncthreads();
        }
    }

    // Phase D: decode, compute boxes, write concat arrays
    if (tid < k) {
        unsigned long long key = buf[tid];
        int e = (int)(key & 0xFFFFFFFFull);
        float mv = unordf(~(unsigned int)(key >> 32));
        int anchor = e / 80;
        int lab = e - anchor * 80;
        int y = anchor / w;
        int x = anchor - y * w;
        const float* bb = p.bb[lvl];
        const float* ct = p.ct[lvl];
        float sf = sigm(ct[(b * h + y) * w + x]);
        float dl = bb[((b * 4 + 0) * h + y) * w + x];
        float dt = bb[((b * 4 + 1) * h + y) * w + x];
        float dr = bb[((b * 4 + 2) * h + y) * w + x];
        float db = bb[((b * 4 + 3) * h + y) * w + x];
        float px = __fmul_rn(__fadd_rn((float)x, 0.5f), (float)stride);
        float py = __fmul_rn(__fadd_rn((float)y, 0.5f), (float)stride);
        float4 bx;
        bx.x = fminf(fmaxf(__fsub_rn(px, dl), 0.0f), IMGSZ);
        bx.y = fminf(fmaxf(__fsub_rn(py, dt), 0.0f), IMGSZ);
        bx.z = fminf(fmaxf(__fadd_rn(px, dr), 0.0f), IMGSZ);
        bx.w = fminf(fmaxf(__fadd_rn(py, db), 0.0f), IMGSZ);
        bool valid = mv > THR;
        int g = b * KTOT + c_outoff[lvl] + tid;
        g_score[g] = valid ? __fmul_rn(mv, sf) : -1.0f;
        g_label[g] = lab;
        g_box[g] = bx;
        g_valid[g] = valid ? 1 : 0;
    }
}

// ---------------------------------------------------------------------------
// Kernel 2: per image block — max-coord, stable sort 4720 (bitonic 8192 SMEM),
// write dets/labels, greedy NMS (chunked, exact semantics), write keep.
// SMEM: union{ u64 sortbuf[8192] (64KB) | float4 offbox[4720] (75520B) } + alive
// ---------------------------------------------------------------------------
#define K2_SMEM 80256

__global__ __launch_bounds__(1024) void k_nms(float* __restrict__ out) {
    const int b = blockIdx.x;
    const int tid = threadIdx.x;
    const int K = KTOT;

    extern __shared__ unsigned char smraw[];
    unsigned long long* sbuf = (unsigned long long*)smraw;
    float4* s_off = (float4*)smraw;
    unsigned char* s_alive = smraw + 75520;

    __shared__ float s_red[32];
    __shared__ float s_maxc;
    __shared__ int s_list[64];
    __shared__ int s_nl;

    // max over all box coords of this image
    const float* bf = (const float*)(g_box + b * K);
    float m = -3.0e38f;
    for (int e = tid; e < K * 4; e += 1024) m = fmaxf(m, bf[e]);
    #pragma unroll
    for (int o = 16; o; o >>= 1) m = fmaxf(m, __shfl_xor_sync(0xFFFFFFFFu, m, o));
    if ((tid & 31) == 0) s_red[tid >> 5] = m;
    __syncthreads();
    if (tid == 0) {
        float v = s_red[0];
        for (int i = 1; i < 32; i++) v = fmaxf(v, s_red[i]);
        s_maxc = v;
    }
    __syncthreads();
    float maxc1 = __fadd_rn(s_maxc, 1.0f);

    // fill keys (score desc, index asc == stable argsort(-scores))
    for (int e = tid; e < 8192; e += 1024) {
        unsigned long long key;
        if (e < K) {
            unsigned int hi = ~ordf(g_score[b * K + e]);
            key = ((unsigned long long)hi << 32) | (unsigned int)e;
        } else {
            key = ~0ull;
        }
        sbuf[e] = key;
    }
    __syncthreads();

    // bitonic sort 8192 in SMEM
    for (int ks2 = 2; ks2 <= 8192; ks2 <<= 1) {
        for (int j = ks2 >> 1; j > 0; j >>= 1) {
            for (int e = tid; e < 8192; e += 1024) {
                int ixj = e ^ j;
                if (ixj > e) {
                    unsigned long long a = sbuf[e], bv = sbuf[ixj];
                    if ((a > bv) == ((e & ks2) == 0)) { sbuf[e] = bv; sbuf[ixj] = a; }
                }
            }
            __syncthreads();
        }
    }

    // stash permutation to global (sbuf gets reused for offboxes)
    for (int r = tid; r < K; r += 1024) g_order[b * K + r] = (int)(sbuf[r] & 0xFFFFFFFFull);
    __syncthreads();

    float* outD = out + (size_t)b * K * 5;
    float* outL = out + (size_t)NB * K * 5 + (size_t)b * K;
    float* outKp = out + (size_t)NB * K * 5 + (size_t)NB * K + (size_t)b * K;

    for (int r = tid; r < K; r += 1024) {
        int src = g_order[b * K + r];
        float4 bx = g_box[b * K + src];
        float sc = g_score[b * K + src];
        int lab = g_label[b * K + src];
        outD[r * 5 + 0] = bx.x;
        outD[r * 5 + 1] = bx.y;
        outD[r * 5 + 2] = bx.z;
        outD[r * 5 + 3] = bx.w;
        outD[r * 5 + 4] = sc;
        outL[r] = (float)lab;
        float off = __fmul_rn((float)lab, maxc1);
        float4 ob;
        ob.x = __fadd_rn(bx.x, off); ob.y = __fadd_rn(bx.y, off);
        ob.z = __fadd_rn(bx.z, off); ob.w = __fadd_rn(bx.w, off);
        s_off[r] = ob;
        s_alive[r] = g_valid[b * K + src];
    }
    __syncthreads();

    // greedy NMS, chunked (exact sequential semantics)
    const int NCH = (K + 63) / 64;
    for (int c = 0; c < NCH; c++) {
        int base = c * 64;
        int end = min(base + 64, K);
        if (tid < 32) {
            if (tid == 0) s_nl = 0;
            for (int i = base; i < end; i++) {
                __syncwarp();
                if (!s_alive[i]) continue;
                if (tid == 0) { s_list[s_nl] = i; s_nl = s_nl + 1; }
                float4 bi = s_off[i];
                for (int j = i + 1 + tid; j < end; j += 32) {
                    if (s_alive[j] && suppresses(bi, s_off[j])) s_alive[j] = 0;
                }
            }
        }
        __syncthreads();
        int nl = s_nl;
        for (int li = 0; li < nl; li++) {
            float4 bi = s_off[s_list[li]];
            for (int j = end + tid; j < K; j += 1024) {
                if (s_alive[j] && suppresses(bi, s_off[j])) s_alive[j] = 0;
            }
        }
        __syncthreads();
    }

    for (int r = tid; r < K; r += 1024) outKp[r] = s_alive[r] ? 1.0f : 0.0f;
}

// ---------------------------------------------------------------------------
extern "C" void kernel_launch(void* const* d_in, const int* in_sizes, int n_in,
                              void* d_out, int out_size) {
    (void)n_in; (void)out_size;
    Ptrs p;
    // Inputs interleaved per level: cls0,bbox0,ctr0,cls1,...  (detect via sizes)
    bool interleaved = (in_sizes[1] == 25600);
    for (int i = 0; i < 5; i++) {
        if (interleaved) {
            p.cls[i] = (const float*)d_in[3 * i + 0];
            p.bb[i]  = (const float*)d_in[3 * i + 1];
            p.ct[i]  = (const float*)d_in[3 * i + 2];
        } else {
            p.cls[i] = (const float*)d_in[i];
            p.bb[i]  = (const float*)d_in[5 + i];
            p.ct[i]  = (const float*)d_in[10 + i];
        }
    }
    k_topk<<<dim3(5, NB), 1024>>>(p);
    cudaFuncSetAttribute(k_nms, cudaFuncAttributeMaxDynamicSharedMemorySize, K2_SMEM);
    k_nms<<<NB, 1024, K2_SMEM>>>((float*)d_out);
}

// round 5
// speedup vs baseline: 1.0106x; 1.0106x over previous
#include <cuda_runtime.h>
#include <math.h>

// Problem constants
#define NB 4          // batch
#define KTOT 4720     // concat candidates per image (1000*4 + 720)
#define IMGSZ 320.0f
#define THR 0.025f
#define IOUTHR 0.5f

typedef unsigned long long u64;
typedef unsigned int u32;

// Per-level tables
__device__ __constant__ int   c_w[5]      = {40, 20, 10, 5, 3};
__device__ __constant__ int   c_A[5]      = {1600, 400, 100, 25, 9};
__device__ __constant__ int   c_stride[5] = {8, 16, 32, 64, 128};
__device__ __constant__ int   c_keyoff[5] = {0, 128000, 160000, 168000, 170000}; // within image
__device__ __constant__ int   c_outoff[5] = {0, 1000, 2000, 3000, 4000};
__device__ __constant__ int   c_k[5]      = {1000, 1000, 1000, 1000, 720};

#define IMG_KEYS 170720
#define NSEG 20
#define HBINS 65536
#define BUFB_CAP 8192

// Scratch (static device globals; zero-initialized — k_select re-zeros g_hist each call)
__device__ u64           g_keys[NB * IMG_KEYS];
__device__ u32           g_hist[NSEG * HBINS];
__device__ float         g_score[NB * KTOT];
__device__ int           g_label[NB * KTOT];
__device__ float4        g_box[NB * KTOT];
__device__ unsigned char g_valid[NB * KTOT];
__device__ int           g_order[NB * KTOT];

struct Ptrs {
    const float* cls[5];
    const float* bb[5];
    const float* ct[5];
};

__device__ __forceinline__ u32 ordf(float f) {
    u32 u = __float_as_uint(f);
    return (u & 0x80000000u) ? ~u : (u | 0x80000000u);
}
__device__ __forceinline__ float unordf(u32 u) {
    return __uint_as_float((u & 0x80000000u) ? (u & 0x7FFFFFFFu) : ~u);
}

// XLA:CPU f32 exp (llvm_ir_runtime GenerateVF32Exp == Eigen/Cephes pexp),
// with FMA contraction as LLVM emits under the rewrite's fast-math flags.
// PROTECT: bit-exact vs reference; do not touch.
__device__ __forceinline__ float xla_cpu_expf(float x) {
    x = fminf(x,  88.3762626647950f);
    x = fmaxf(x, -88.3762626647949f);
    float fx = floorf(__fmaf_rn(x, 1.44269504088896341f, 0.5f));
    float r = __fmaf_rn(fx, -0.693359375f, x);
    r = __fmaf_rn(fx, 2.12194440e-4f, r);
    float r2 = __fmul_rn(r, r);
    float y = 1.9875691500e-4f;
    y = __fmaf_rn(y, r, 1.3981999507e-3f);
    y = __fmaf_rn(y, r, 8.3334519073e-3f);
    y = __fmaf_rn(y, r, 4.1665795894e-2f);
    y = __fmaf_rn(y, r, 1.6666665459e-1f);
    y = __fmaf_rn(y, r, 5.0000001201e-1f);
    y = __fmaf_rn(y, r2, r);
    y = __fadd_rn(y, 1.0f);
    int n = (int)fx;
    float s = __int_as_float((u32)(n + 127) << 23);
    return __fmul_rn(y, s);
}
__device__ __forceinline__ float sigm(float x) {
    return __fdiv_rn(1.0f, __fadd_rn(1.0f, xla_cpu_expf(-x)));
}

// IoU on offset boxes, exact reference float op order, every op separately rounded.
__device__ __forceinline__ bool suppresses(const float4 a, const float4 b) {
    float aa = __fmul_rn(__fsub_rn(a.z, a.x), __fsub_rn(a.w, a.y));
    float ab = __fmul_rn(__fsub_rn(b.z, b.x), __fsub_rn(b.w, b.y));
    float ltx = fmaxf(a.x, b.x), lty = fmaxf(a.y, b.y);
    float rbx = fminf(a.z, b.z), rby = fminf(a.w, b.w);
    float w = fmaxf(__fsub_rn(rbx, ltx), 0.0f), h = fmaxf(__fsub_rn(rby, lty), 0.0f);
    float inter = __fmul_rn(w, h);
    float uni = __fsub_rn(__fadd_rn(aa, ab), inter);
    float iou = (uni > 0.0f) ? __fdiv_rn(inter, uni) : 0.0f;
    return iou > IOUTHR;
}

// Bitonic sort of buf[0..P) in SMEM, P power of 2, called by all 1024 threads.
__device__ __forceinline__ void bitonic_smem(u64* buf, int P, int tid) {
    for (int ks2 = 2; ks2 <= P; ks2 <<= 1) {
        for (int j = ks2 >> 1; j > 0; j >>= 1) {
            for (int e = tid; e < P; e += 1024) {
                int ixj = e ^ j;
                if (ixj > e) {
                    u64 a = buf[e], bv = buf[ixj];
                    if ((a > bv) == ((e & ks2) == 0)) { buf[e] = bv; buf[ixj] = a; }
                }
            }
            __syncthreads();
        }
    }
}

// ---------------------------------------------------------------------------
// Kernel A: wide pass — sigmoid keys (coalesced cls reads, scattered key writes)
// + 16-bit-prefix global histogram per (b,lvl) segment.
// grid: (ceil(Nmax/1024), 5, NB), block 256, 4 elems/thread.
// ---------------------------------------------------------------------------
__global__ __launch_bounds__(256) void k_score(Ptrs p) {
    const int lvl = blockIdx.y;
    const int b = blockIdx.z;
    const int A = c_A[lvl];
    const int N = A * 80;
    const int base = blockIdx.x * 1024;
    if (base >= N) return;

    const float* cls = p.cls[lvl] + (size_t)b * N;   // [80, h, w] slab
    u64* keys = g_keys + b * IMG_KEYS + c_keyoff[lvl];
    u32* hist = g_hist + (b * 5 + lvl) * HBINS;

    #pragma unroll
    for (int t = 0; t < 4; t++) {
        int i = base + t * 256 + threadIdx.x;   // memory order: i = c*A + anchor
        if (i < N) {
            float f = cls[i];
            int c = i / A;
            int anchor = i - c * A;
            int e = anchor * 80 + c;            // reference flatten order
            float s = sigm(f);
            float mv = (s > THR) ? s : -1.0f;
            u32 hi = ~ordf(mv);
            keys[e] = ((u64)hi << 32) | (u32)e;
            atomicAdd(&hist[hi >> 16], 1u);
        }
    }
}

// ---------------------------------------------------------------------------
// Kernel B: per (lvl, b) block — find boundary prefix via 65536-bin scan,
// gather candidates, two small bitonic sorts, exact decode + emit.
// dyn smem: bufB[8192] u64 + bufA[1024] u64 = 73728 bytes.
// ---------------------------------------------------------------------------
#define KSEL_SMEM ((BUFB_CAP + 1024) * 8)

__global__ __launch_bounds__(1024) void k_select(Ptrs p) {
    const int lvl = blockIdx.x;
    const int b = blockIdx.y;
    const int tid = threadIdx.x;
    const int lane = tid & 31, wid = tid >> 5;

    const int w = c_w[lvl];
    const int A = c_A[lvl];
    const int N = A * 80;
    const int k = c_k[lvl];
    const int stride = c_stride[lvl];

    u64* keys = g_keys + b * IMG_KEYS + c_keyoff[lvl];
    u32* hist = g_hist + (b * 5 + lvl) * HBINS;

    extern __shared__ u64 dyn[];
    u64* bufB = dyn;               // boundary-bin candidates
    u64* bufA = dyn + BUFB_CAP;    // final top-k workspace (1024)

    __shared__ u32 s_wsum[32];
    __shared__ int s_B, s_kp;
    __shared__ u32 s_cA, s_cB;

    // 1) per-thread sum of 64 bins, block exclusive scan, find crossing
    const int b0 = tid * 64;
    u32 st = 0;
    #pragma unroll 8
    for (int j = 0; j < 64; j++) st += hist[b0 + j];
    u32 incl = st;
    #pragma unroll
    for (int o = 1; o < 32; o <<= 1) {
        u32 v = __shfl_up_sync(0xFFFFFFFFu, incl, o);
        if (lane >= o) incl += v;
    }
    if (lane == 31) s_wsum[wid] = incl;
    __syncthreads();
    if (wid == 0) {
        u32 v = s_wsum[lane];
        #pragma unroll
        for (int o = 1; o < 32; o <<= 1) {
            u32 t2 = __shfl_up_sync(0xFFFFFFFFu, v, o);
            if (lane >= o) v += t2;
        }
        s_wsum[lane] = v;
    }
    __syncthreads();
    u32 myexcl = (wid ? s_wsum[wid - 1] : 0u) + (incl - st);
    if (myexcl < (u32)k && myexcl + st >= (u32)k) {
        u32 cum = myexcl;
        for (int j = 0; j < 64; j++) {
            u32 c2 = hist[b0 + j];
            if (cum + c2 >= (u32)k) { s_B = b0 + j; s_kp = k - (int)cum; break; }
            cum += c2;
        }
    }
    __syncthreads();
    const int B = s_B;
    const int kp = s_kp;

    // re-zero hist for next graph replay (no further reads)
    #pragma unroll 8
    for (int j = 0; j < 64; j++) hist[b0 + j] = 0;

    // 2) gather: prefix < B definitely in; prefix == B to boundary buffer
    if (tid == 0) { s_cA = 0; s_cB = 0; }
    __syncthreads();
    for (int e = tid; e < N; e += 1024) {
        u64 key = keys[e];
        int pre = (int)(key >> 48);
        if (pre < B) {
            u32 pos = atomicAdd(&s_cA, 1u);
            bufA[pos] = key;
        } else if (pre == B) {
            u32 pos = atomicAdd(&s_cB, 1u);
            if (pos < BUFB_CAP) bufB[pos] = key;
        }
    }
    __syncthreads();
    int nB = (int)min(s_cB, (u32)BUFB_CAP);
    u32 cA = s_cA;

    // 3) sort boundary bin, append smallest kp to bufA
    int P = 2;
    while (P < nB) P <<= 1;
    for (int e = tid; e < P; e += 1024) if (e >= nB) bufB[e] = ~0ull;
    __syncthreads();
    bitonic_smem(bufB, P, tid);
    if (tid < kp) bufA[cA + tid] = bufB[tid];
    if (tid >= k) bufA[tid] = ~0ull;   // pad to 1024
    __syncthreads();

    // 4) final sort of k keys (ascending key == score desc, idx asc)
    bitonic_smem(bufA, 1024, tid);

    // 5) decode + emit (exact float ops — PROTECT)
    if (tid < k) {
        u64 key = bufA[tid];
        int e = (int)(key & 0xFFFFFFFFull);
        float mv = unordf(~(u32)(key >> 32));
        int anchor = e / 80;
        int lab = e - anchor * 80;
        int y = anchor / w;
        int x = anchor - y * w;
        const float* bb = p.bb[lvl];
        const float* ct = p.ct[lvl];
        float sf = sigm(ct[(size_t)b * A + anchor]);
        float dl = bb[((size_t)b * 4 + 0) * A + anchor];
        float dt = bb[((size_t)b * 4 + 1) * A + anchor];
        float dr = bb[((size_t)b * 4 + 2) * A + anchor];
        float db = bb[((size_t)b * 4 + 3) * A + anchor];
        float px = __fmul_rn(__fadd_rn((float)x, 0.5f), (float)stride);
        float py = __fmul_rn(__fadd_rn((float)y, 0.5f), (float)stride);
        float4 bx;
        bx.x = fminf(fmaxf(__fsub_rn(px, dl), 0.0f), IMGSZ);
        bx.y = fminf(fmaxf(__fsub_rn(py, dt), 0.0f), IMGSZ);
        bx.z = fminf(fmaxf(__fadd_rn(px, dr), 0.0f), IMGSZ);
        bx.w = fminf(fmaxf(__fadd_rn(py, db), 0.0f), IMGSZ);
        bool valid = mv > THR;
        int g = b * KTOT + c_outoff[lvl] + tid;
        g_score[g] = valid ? __fmul_rn(mv, sf) : -1.0f;
        g_label[g] = lab;
        g_box[g] = bx;
        g_valid[g] = valid ? 1 : 0;
    }
}

// ---------------------------------------------------------------------------
// Kernel 2: per image block — max-coord, stable sort 4720 (bitonic 8192 SMEM),
// write dets/labels, greedy NMS (chunked, exact semantics), write keep.
// (unchanged from passing version — PROTECT semantics)
// ---------------------------------------------------------------------------
#define K2_SMEM 80256

__global__ __launch_bounds__(1024) void k_nms(float* __restrict__ out) {
    const int b = blockIdx.x;
    const int tid = threadIdx.x;
    const int K = KTOT;

    extern __shared__ unsigned char smraw[];
    u64* sbuf = (u64*)smraw;
    float4* s_off = (float4*)smraw;
    unsigned char* s_alive = smraw + 75520;

    __shared__ float s_red[32];
    __shared__ float s_maxc;
    __shared__ int s_list[64];
    __shared__ int s_nl;

    const float* bf = (const float*)(g_box + b * K);
    float m = -3.0e38f;
    for (int e = tid; e < K * 4; e += 1024) m = fmaxf(m, bf[e]);
    #pragma unroll
    for (int o = 16; o; o >>= 1) m = fmaxf(m, __shfl_xor_sync(0xFFFFFFFFu, m, o));
    if ((tid & 31) == 0) s_red[tid >> 5] = m;
    __syncthreads();
    if (tid == 0) {
        float v = s_red[0];
        for (int i = 1; i < 32; i++) v = fmaxf(v, s_red[i]);
        s_maxc = v;
    }
    __syncthreads();
    float maxc1 = __fadd_rn(s_maxc, 1.0f);

    for (int e = tid; e < 8192; e += 1024) {
        u64 key;
        if (e < K) {
            u32 hi = ~ordf(g_score[b * K + e]);
            key = ((u64)hi << 32) | (u32)e;
        } else {
            key = ~0ull;
        }
        sbuf[e] = key;
    }
    __syncthreads();

    for (int ks2 = 2; ks2 <= 8192; ks2 <<= 1) {
        for (int j = ks2 >> 1; j > 0; j >>= 1) {
            for (int e = tid; e < 8192; e += 1024) {
                int ixj = e ^ j;
                if (ixj > e) {
                    u64 a = sbuf[e], bv = sbuf[ixj];
                    if ((a > bv) == ((e & ks2) == 0)) { sbuf[e] = bv; sbuf[ixj] = a; }
                }
            }
            __syncthreads();
        }
    }

    for (int r = tid; r < K; r += 1024) g_order[b * K + r] = (int)(sbuf[r] & 0xFFFFFFFFull);
    __syncthreads();

    float* outD = out + (size_t)b * K * 5;
    float* outL = out + (size_t)NB * K * 5 + (size_t)b * K;
    float* outKp = out + (size_t)NB * K * 5 + (size_t)NB * K + (size_t)b * K;

    for (int r = tid; r < K; r += 1024) {
        int src = g_order[b * K + r];
        float4 bx = g_box[b * K + src];
        float sc = g_score[b * K + src];
        int lab = g_label[b * K + src];
        outD[r * 5 + 0] = bx.x;
        outD[r * 5 + 1] = bx.y;
        outD[r * 5 + 2] = bx.z;
        outD[r * 5 + 3] = bx.w;
        outD[r * 5 + 4] = sc;
        outL[r] = (float)lab;
        float off = __fmul_rn((float)lab, maxc1);
        float4 ob;
        ob.x = __fadd_rn(bx.x, off); ob.y = __fadd_rn(bx.y, off);
        ob.z = __fadd_rn(bx.z, off); ob.w = __fadd_rn(bx.w, off);
        s_off[r] = ob;
        s_alive[r] = g_valid[b * K + src];
    }
    __syncthreads();

    const int NCH = (K + 63) / 64;
    for (int c = 0; c < NCH; c++) {
        int base = c * 64;
        int end = min(base + 64, K);
        if (tid < 32) {
            if (tid == 0) s_nl = 0;
            for (int i = base; i < end; i++) {
                __syncwarp();
                if (!s_alive[i]) continue;
                if (tid == 0) { s_list[s_nl] = i; s_nl = s_nl + 1; }
                float4 bi = s_off[i];
                for (int j = i + 1 + tid; j < end; j += 32) {
                    if (s_alive[j] && suppresses(bi, s_off[j])) s_alive[j] = 0;
                }
            }
        }
        __syncthreads();
        int nl = s_nl;
        for (int li = 0; li < nl; li++) {
            float4 bi = s_off[s_list[li]];
            for (int j = end + tid; j < K; j += 1024) {
                if (s_alive[j] && suppresses(bi, s_off[j])) s_alive[j] = 0;
            }
        }
        __syncthreads();
    }

    for (int r = tid; r < K; r += 1024) outKp[r] = s_alive[r] ? 1.0f : 0.0f;
}

// ---------------------------------------------------------------------------
extern "C" void kernel_launch(void* const* d_in, const int* in_sizes, int n_in,
                              void* d_out, int out_size) {
    (void)n_in; (void)out_size;
    Ptrs p;
    bool interleaved = (in_sizes[1] == 25600);
    for (int i = 0; i < 5; i++) {
        if (interleaved) {
            p.cls[i] = (const float*)d_in[3 * i + 0];
            p.bb[i]  = (const float*)d_in[3 * i + 1];
            p.ct[i]  = (const float*)d_in[3 * i + 2];
        } else {
            p.cls[i] = (const float*)d_in[i];
            p.bb[i]  = (const float*)d_in[5 + i];
            p.ct[i]  = (const float*)d_in[10 + i];
        }
    }
    // k_score covers the largest level with blockIdx.x; smaller levels early-exit.
    k_score<<<dim3(125, 5, NB), 256>>>(p);
    cudaFuncSetAttribute(k_select, cudaFuncAttributeMaxDynamicSharedMemorySize, KSEL_SMEM);
    k_select<<<dim3(5, NB), 1024, KSEL_SMEM>>>(p);
    cudaFuncSetAttribute(k_nms, cudaFuncAttributeMaxDynamicSharedMemorySize, K2_SMEM);
    k_nms<<<NB, 1024, K2_SMEM>>>((float*)d_out);
}

// round 6
// speedup vs baseline: 12.6981x; 12.5652x over previous
#include <cuda_runtime.h>
#include <math.h>

// Problem constants
#define NB 4          // batch
#define KTOT 4720     // concat candidates per image (1000*4 + 720)
#define IMGSZ 320.0f
#define THR 0.025f
#define IOUTHR 0.5f
#define NCLS 80

typedef unsigned long long u64;
typedef unsigned int u32;
typedef unsigned short u16;
typedef unsigned char u8;

// Per-level tables
__device__ __constant__ int   c_w[5]      = {40, 20, 10, 5, 3};
__device__ __constant__ int   c_A[5]      = {1600, 400, 100, 25, 9};
__device__ __constant__ int   c_stride[5] = {8, 16, 32, 64, 128};
__device__ __constant__ int   c_keyoff[5] = {0, 128000, 160000, 168000, 170000}; // within image
__device__ __constant__ int   c_outoff[5] = {0, 1000, 2000, 3000, 4000};
__device__ __constant__ int   c_k[5]      = {1000, 1000, 1000, 1000, 720};

#define IMG_KEYS 170720
#define NSEG 20
#define HBINS 65536
#define BUFB_CAP 8192

// Scratch (static device globals; zero-initialized — k_select re-zeros g_hist each call)
__device__ u64           g_keys[NB * IMG_KEYS];
__device__ u32           g_hist[NSEG * HBINS];
__device__ float         g_score[NB * KTOT];
__device__ int           g_label[NB * KTOT];
__device__ float4        g_box[NB * KTOT];
__device__ u8            g_valid[NB * KTOT];
__device__ int           g_order[NB * KTOT];

struct Ptrs {
    const float* cls[5];
    const float* bb[5];
    const float* ct[5];
};

__device__ __forceinline__ u32 ordf(float f) {
    u32 u = __float_as_uint(f);
    return (u & 0x80000000u) ? ~u : (u | 0x80000000u);
}
__device__ __forceinline__ float unordf(u32 u) {
    return __uint_as_float((u & 0x80000000u) ? (u & 0x7FFFFFFFu) : ~u);
}

// XLA:CPU f32 exp (Eigen/Cephes pexp) with FMA contraction. PROTECT: bit-exact.
__device__ __forceinline__ float xla_cpu_expf(float x) {
    x = fminf(x,  88.3762626647950f);
    x = fmaxf(x, -88.3762626647949f);
    float fx = floorf(__fmaf_rn(x, 1.44269504088896341f, 0.5f));
    float r = __fmaf_rn(fx, -0.693359375f, x);
    r = __fmaf_rn(fx, 2.12194440e-4f, r);
    float r2 = __fmul_rn(r, r);
    float y = 1.9875691500e-4f;
    y = __fmaf_rn(y, r, 1.3981999507e-3f);
    y = __fmaf_rn(y, r, 8.3334519073e-3f);
    y = __fmaf_rn(y, r, 4.1665795894e-2f);
    y = __fmaf_rn(y, r, 1.6666665459e-1f);
    y = __fmaf_rn(y, r, 5.0000001201e-1f);
    y = __fmaf_rn(y, r2, r);
    y = __fadd_rn(y, 1.0f);
    int n = (int)fx;
    float s = __int_as_float((u32)(n + 127) << 23);
    return __fmul_rn(y, s);
}
__device__ __forceinline__ float sigm(float x) {
    return __fdiv_rn(1.0f, __fadd_rn(1.0f, xla_cpu_expf(-x)));
}

// IoU on offset boxes, exact reference float op order. PROTECT.
__device__ __forceinline__ bool suppresses(const float4 a, const float4 b) {
    float aa = __fmul_rn(__fsub_rn(a.z, a.x), __fsub_rn(a.w, a.y));
    float ab = __fmul_rn(__fsub_rn(b.z, b.x), __fsub_rn(b.w, b.y));
    float ltx = fmaxf(a.x, b.x), lty = fmaxf(a.y, b.y);
    float rbx = fminf(a.z, b.z), rby = fminf(a.w, b.w);
    float w = fmaxf(__fsub_rn(rbx, ltx), 0.0f), h = fmaxf(__fsub_rn(rby, lty), 0.0f);
    float inter = __fmul_rn(w, h);
    float uni = __fsub_rn(__fadd_rn(aa, ab), inter);
    float iou = (uni > 0.0f) ? __fdiv_rn(inter, uni) : 0.0f;
    return iou > IOUTHR;
}

// Bitonic sort of buf[0..P) in SMEM, P power of 2, all 1024 threads.
__device__ __forceinline__ void bitonic_smem(u64* buf, int P, int tid) {
    for (int ks2 = 2; ks2 <= P; ks2 <<= 1) {
        for (int j = ks2 >> 1; j > 0; j >>= 1) {
            for (int e = tid; e < P; e += 1024) {
                int ixj = e ^ j;
                if (ixj > e) {
                    u64 a = buf[e], bv = buf[ixj];
                    if ((a > bv) == ((e & ks2) == 0)) { buf[e] = bv; buf[ixj] = a; }
                }
            }
            __syncthreads();
        }
    }
}

// ---------------------------------------------------------------------------
// Kernel A: wide pass — sigmoid keys + 16-bit-prefix histogram per segment.
// ---------------------------------------------------------------------------
__global__ __launch_bounds__(256) void k_score(Ptrs p) {
    const int lvl = blockIdx.y;
    const int b = blockIdx.z;
    const int A = c_A[lvl];
    const int N = A * 80;
    const int base = blockIdx.x * 1024;
    if (base >= N) return;

    const float* cls = p.cls[lvl] + (size_t)b * N;
    u64* keys = g_keys + b * IMG_KEYS + c_keyoff[lvl];
    u32* hist = g_hist + (b * 5 + lvl) * HBINS;

    #pragma unroll
    for (int t = 0; t < 4; t++) {
        int i = base + t * 256 + threadIdx.x;
        if (i < N) {
            float f = cls[i];
            int c = i / A;
            int anchor = i - c * A;
            int e = anchor * 80 + c;
            float s = sigm(f);
            float mv = (s > THR) ? s : -1.0f;
            u32 hi = ~ordf(mv);
            keys[e] = ((u64)hi << 32) | (u32)e;
            atomicAdd(&hist[hi >> 16], 1u);
        }
    }
}

// ---------------------------------------------------------------------------
// Kernel B: per (lvl, b) block — boundary prefix via 65536-bin scan, gather,
// two bitonic sorts, exact decode + emit.
// ---------------------------------------------------------------------------
#define KSEL_SMEM ((BUFB_CAP + 1024) * 8)

__global__ __launch_bounds__(1024) void k_select(Ptrs p) {
    const int lvl = blockIdx.x;
    const int b = blockIdx.y;
    const int tid = threadIdx.x;
    const int lane = tid & 31, wid = tid >> 5;

    const int w = c_w[lvl];
    const int A = c_A[lvl];
    const int N = A * 80;
    const int k = c_k[lvl];
    const int stride = c_stride[lvl];

    u64* keys = g_keys + b * IMG_KEYS + c_keyoff[lvl];
    u32* hist = g_hist + (b * 5 + lvl) * HBINS;

    extern __shared__ u64 dyn[];
    u64* bufB = dyn;
    u64* bufA = dyn + BUFB_CAP;

    __shared__ u32 s_wsum[32];
    __shared__ int s_B, s_kp;
    __shared__ u32 s_cA, s_cB;

    const int b0 = tid * 64;
    u32 st = 0;
    #pragma unroll 8
    for (int j = 0; j < 64; j++) st += hist[b0 + j];
    u32 incl = st;
    #pragma unroll
    for (int o = 1; o < 32; o <<= 1) {
        u32 v = __shfl_up_sync(0xFFFFFFFFu, incl, o);
        if (lane >= o) incl += v;
    }
    if (lane == 31) s_wsum[wid] = incl;
    __syncthreads();
    if (wid == 0) {
        u32 v = s_wsum[lane];
        #pragma unroll
        for (int o = 1; o < 32; o <<= 1) {
            u32 t2 = __shfl_up_sync(0xFFFFFFFFu, v, o);
            if (lane >= o) v += t2;
        }
        s_wsum[lane] = v;
    }
    __syncthreads();
    u32 myexcl = (wid ? s_wsum[wid - 1] : 0u) + (incl - st);
    if (myexcl < (u32)k && myexcl + st >= (u32)k) {
        u32 cum = myexcl;
        for (int j = 0; j < 64; j++) {
            u32 c2 = hist[b0 + j];
            if (cum + c2 >= (u32)k) { s_B = b0 + j; s_kp = k - (int)cum; break; }
            cum += c2;
        }
    }
    __syncthreads();
    const int B = s_B;
    const int kp = s_kp;

    #pragma unroll 8
    for (int j = 0; j < 64; j++) hist[b0 + j] = 0;

    if (tid == 0) { s_cA = 0; s_cB = 0; }
    __syncthreads();
    for (int e = tid; e < N; e += 1024) {
        u64 key = keys[e];
        int pre = (int)(key >> 48);
        if (pre < B) {
            u32 pos = atomicAdd(&s_cA, 1u);
            bufA[pos] = key;
        } else if (pre == B) {
            u32 pos = atomicAdd(&s_cB, 1u);
            if (pos < BUFB_CAP) bufB[pos] = key;
        }
    }
    __syncthreads();
    int nB = (int)min(s_cB, (u32)BUFB_CAP);
    u32 cA = s_cA;

    int P = 2;
    while (P < nB) P <<= 1;
    for (int e = tid; e < P; e += 1024) if (e >= nB) bufB[e] = ~0ull;
    __syncthreads();
    bitonic_smem(bufB, P, tid);
    if (tid < kp) bufA[cA + tid] = bufB[tid];
    if (tid >= k) bufA[tid] = ~0ull;
    __syncthreads();

    bitonic_smem(bufA, 1024, tid);

    if (tid < k) {
        u64 key = bufA[tid];
        int e = (int)(key & 0xFFFFFFFFull);
        float mv = unordf(~(u32)(key >> 32));
        int anchor = e / 80;
        int lab = e - anchor * 80;
        int y = anchor / w;
        int x = anchor - y * w;
        const float* bb = p.bb[lvl];
        const float* ct = p.ct[lvl];
        float sf = sigm(ct[(size_t)b * A + anchor]);
        float dl = bb[((size_t)b * 4 + 0) * A + anchor];
        float dt = bb[((size_t)b * 4 + 1) * A + anchor];
        float dr = bb[((size_t)b * 4 + 2) * A + anchor];
        float db = bb[((size_t)b * 4 + 3) * A + anchor];
        float px = __fmul_rn(__fadd_rn((float)x, 0.5f), (float)stride);
        float py = __fmul_rn(__fadd_rn((float)y, 0.5f), (float)stride);
        float4 bx;
        bx.x = fminf(fmaxf(__fsub_rn(px, dl), 0.0f), IMGSZ);
        bx.y = fminf(fmaxf(__fsub_rn(py, dt), 0.0f), IMGSZ);
        bx.z = fminf(fmaxf(__fadd_rn(px, dr), 0.0f), IMGSZ);
        bx.w = fminf(fmaxf(__fadd_rn(py, db), 0.0f), IMGSZ);
        bool valid = mv > THR;
        int g = b * KTOT + c_outoff[lvl] + tid;
        g_score[g] = valid ? __fmul_rn(mv, sf) : -1.0f;
        g_label[g] = lab;
        g_box[g] = bx;
        g_valid[g] = valid ? 1 : 0;
    }
}

// ---------------------------------------------------------------------------
// Kernel C: per image block — max-coord, stable sort 4720 (bitonic 8192 SMEM),
// write dets/labels, then PER-CLASS greedy NMS (exact decomposition: offset
// trick makes cross-class IoU exactly 0, so greedy suppression is block-
// diagonal by class; class-local order == global order restricted to class).
// dyn smem: union{sbuf 8192 u64 | s_off float4[4720]} + alive + lab + lists.
// ---------------------------------------------------------------------------
#define OFF_ALIVE 75520
#define OFF_LAB   (OFF_ALIVE + KTOT)
#define OFF_LIST  (OFF_LAB + KTOT)      // u16[4720], 2-byte aligned (75520+9440 even)
#define K2_SMEM   (OFF_LIST + KTOT * 2)

__global__ __launch_bounds__(1024) void k_nms(float* __restrict__ out) {
    const int b = blockIdx.x;
    const int tid = threadIdx.x;
    const int K = KTOT;
    const int lane = tid & 31, wid = tid >> 5;

    extern __shared__ unsigned char smraw[];
    u64* sbuf = (u64*)smraw;
    float4* s_off = (float4*)smraw;
    u8* s_alive = smraw + OFF_ALIVE;
    u8* s_lab = smraw + OFF_LAB;
    u16* s_list = (u16*)(smraw + OFF_LIST);

    __shared__ float s_red[32];
    __shared__ float s_maxc;
    __shared__ int s_cnt[NCLS];
    __shared__ int s_ofs[NCLS];

    // max over all box coords of this image
    const float* bf = (const float*)(g_box + b * K);
    float m = -3.0e38f;
    for (int e = tid; e < K * 4; e += 1024) m = fmaxf(m, bf[e]);
    #pragma unroll
    for (int o = 16; o; o >>= 1) m = fmaxf(m, __shfl_xor_sync(0xFFFFFFFFu, m, o));
    if (lane == 0) s_red[wid] = m;
    if (tid < NCLS) s_cnt[tid] = 0;
    __syncthreads();
    if (tid == 0) {
        float v = s_red[0];
        for (int i = 1; i < 32; i++) v = fmaxf(v, s_red[i]);
        s_maxc = v;
    }
    __syncthreads();
    float maxc1 = __fadd_rn(s_maxc, 1.0f);

    // keys: score desc, index asc == stable argsort(-scores)
    for (int e = tid; e < 8192; e += 1024) {
        u64 key;
        if (e < K) {
            u32 hi = ~ordf(g_score[b * K + e]);
            key = ((u64)hi << 32) | (u32)e;
        } else {
            key = ~0ull;
        }
        sbuf[e] = key;
    }
    __syncthreads();

    bitonic_smem(sbuf, 8192, tid);

    for (int r = tid; r < K; r += 1024) g_order[b * K + r] = (int)(sbuf[r] & 0xFFFFFFFFull);
    __syncthreads();

    float* outD = out + (size_t)b * K * 5;
    float* outL = out + (size_t)NB * K * 5 + (size_t)b * K;
    float* outKp = out + (size_t)NB * K * 5 + (size_t)NB * K + (size_t)b * K;

    for (int r = tid; r < K; r += 1024) {
        int src = g_order[b * K + r];
        float4 bx = g_box[b * K + src];
        float sc = g_score[b * K + src];
        int lab = g_label[b * K + src];
        outD[r * 5 + 0] = bx.x;
        outD[r * 5 + 1] = bx.y;
        outD[r * 5 + 2] = bx.z;
        outD[r * 5 + 3] = bx.w;
        outD[r * 5 + 4] = sc;
        outL[r] = (float)lab;
        float off = __fmul_rn((float)lab, maxc1);
        float4 ob;
        ob.x = __fadd_rn(bx.x, off); ob.y = __fadd_rn(bx.y, off);
        ob.z = __fadd_rn(bx.z, off); ob.w = __fadd_rn(bx.w, off);
        s_off[r] = ob;
        s_alive[r] = g_valid[b * K + src];
        s_lab[r] = (u8)lab;
        atomicAdd(&s_cnt[lab], 1);
    }
    __syncthreads();

    // exclusive scan of class counts (80 values, serial is trivial)
    if (tid == 0) {
        int acc = 0;
        for (int c = 0; c < NCLS; c++) { s_ofs[c] = acc; acc += s_cnt[c]; }
    }
    __syncthreads();

    // ordered bucket fill: thread c collects its class's rows in sorted order
    if (tid < NCLS) {
        int c = tid;
        int w0 = s_ofs[c];
        int n = 0;
        for (int r = 0; r < K; r++) {
            if (s_lab[r] == (u8)c) s_list[w0 + n++] = (u16)r;
        }
    }
    __syncthreads();

    // per-class greedy NMS, one class per warp (classes partition rows)
    for (int c = wid; c < NCLS; c += 32) {
        int base = s_ofs[c];
        int n = s_cnt[c];
        for (int i = 0; i < n; i++) {
            int ri = s_list[base + i];
            if (s_alive[ri]) {
                float4 bi = s_off[ri];
                for (int j = i + 1 + lane; j < n; j += 32) {
                    int rj = s_list[base + j];
                    if (s_alive[rj] && suppresses(bi, s_off[rj])) s_alive[rj] = 0;
                }
            }
            __syncwarp();
        }
    }
    __syncthreads();

    for (int r = tid; r < K; r += 1024) outKp[r] = s_alive[r] ? 1.0f : 0.0f;
}

// ---------------------------------------------------------------------------
extern "C" void kernel_launch(void* const* d_in, const int* in_sizes, int n_in,
                              void* d_out, int out_size) {
    (void)n_in; (void)out_size;
    Ptrs p;
    bool interleaved = (in_sizes[1] == 25600);
    for (int i = 0; i < 5; i++) {
        if (interleaved) {
            p.cls[i] = (const float*)d_in[3 * i + 0];
            p.bb[i]  = (const float*)d_in[3 * i + 1];
            p.ct[i]  = (const float*)d_in[3 * i + 2];
        } else {
            p.cls[i] = (const float*)d_in[i];
            p.bb[i]  = (const float*)d_in[5 + i];
            p.ct[i]  = (const float*)d_in[10 + i];
        }
    }
    k_score<<<dim3(125, 5, NB), 256>>>(p);
    cudaFuncSetAttribute(k_select, cudaFuncAttributeMaxDynamicSharedMemorySize, KSEL_SMEM);
    k_select<<<dim3(5, NB), 1024, KSEL_SMEM>>>(p);
    cudaFuncSetAttribute(k_nms, cudaFuncAttributeMaxDynamicSharedMemorySize, K2_SMEM);
    k_nms<<<NB, 1024, K2_SMEM>>>((float*)d_out);
}

// round 7
// speedup vs baseline: 18.0565x; 1.4220x over previous
#include <cuda_runtime.h>
#include <math.h>

// Problem constants
#define NB 4          // batch
#define KTOT 4720     // concat candidates per image (1000*4 + 720)
#define IMGSZ 320.0f
#define THR 0.025f
#define IOUTHR 0.5f
#define NCLS 80

typedef unsigned long long u64;
typedef unsigned int u32;
typedef unsigned short u16;
typedef unsigned char u8;

// Per-level tables
__device__ __constant__ int   c_w[5]      = {40, 20, 10, 5, 3};
__device__ __constant__ int   c_A[5]      = {1600, 400, 100, 25, 9};
__device__ __constant__ int   c_stride[5] = {8, 16, 32, 64, 128};
__device__ __constant__ int   c_outoff[5] = {0, 1000, 2000, 3000, 4000};
__device__ __constant__ int   c_k[5]      = {1000, 1000, 1000, 1000, 720};

#define NSEG 20
#define HBITS 14
#define HBINS (1 << HBITS)
#define HSHIFT (32 - HBITS)
#define BUFB_CAP 8192

// Scratch (static device globals; k_select re-zeros g_hist each call)
__device__ u32           g_hist[NSEG * HBINS];
__device__ u64           g_skey[NB * KTOT];   // (~ordf(final_score)<<32) | per-image index
__device__ float4        g_box[NB * KTOT];
__device__ u8            g_lab[NB * KTOT];
__device__ u8            g_valid[NB * KTOT];

struct Ptrs {
    const float* cls[5];
    const float* bb[5];
    const float* ct[5];
};

__device__ __forceinline__ u32 ordf(float f) {
    u32 u = __float_as_uint(f);
    return (u & 0x80000000u) ? ~u : (u | 0x80000000u);
}
__device__ __forceinline__ float unordf(u32 u) {
    return __uint_as_float((u & 0x80000000u) ? (u & 0x7FFFFFFFu) : ~u);
}

// XLA:CPU f32 exp (Eigen/Cephes pexp) with FMA contraction. PROTECT: bit-exact.
__device__ __forceinline__ float xla_cpu_expf(float x) {
    x = fminf(x,  88.3762626647950f);
    x = fmaxf(x, -88.3762626647949f);
    float fx = floorf(__fmaf_rn(x, 1.44269504088896341f, 0.5f));
    float r = __fmaf_rn(fx, -0.693359375f, x);
    r = __fmaf_rn(fx, 2.12194440e-4f, r);
    float r2 = __fmul_rn(r, r);
    float y = 1.9875691500e-4f;
    y = __fmaf_rn(y, r, 1.3981999507e-3f);
    y = __fmaf_rn(y, r, 8.3334519073e-3f);
    y = __fmaf_rn(y, r, 4.1665795894e-2f);
    y = __fmaf_rn(y, r, 1.6666665459e-1f);
    y = __fmaf_rn(y, r, 5.0000001201e-1f);
    y = __fmaf_rn(y, r2, r);
    y = __fadd_rn(y, 1.0f);
    int n = (int)fx;
    float s = __int_as_float((u32)(n + 127) << 23);
    return __fmul_rn(y, s);
}
__device__ __forceinline__ float sigm(float x) {
    return __fdiv_rn(1.0f, __fadd_rn(1.0f, xla_cpu_expf(-x)));
}

// IoU on offset boxes, exact reference float op order. PROTECT.
__device__ __forceinline__ bool suppresses(const float4 a, const float4 b) {
    float aa = __fmul_rn(__fsub_rn(a.z, a.x), __fsub_rn(a.w, a.y));
    float ab = __fmul_rn(__fsub_rn(b.z, b.x), __fsub_rn(b.w, b.y));
    float ltx = fmaxf(a.x, b.x), lty = fmaxf(a.y, b.y);
    float rbx = fminf(a.z, b.z), rby = fminf(a.w, b.w);
    float w = fmaxf(__fsub_rn(rbx, ltx), 0.0f), h = fmaxf(__fsub_rn(rby, lty), 0.0f);
    float inter = __fmul_rn(w, h);
    float uni = __fsub_rn(__fadd_rn(aa, ab), inter);
    float iou = (uni > 0.0f) ? __fdiv_rn(inter, uni) : 0.0f;
    return iou > IOUTHR;
}

// Generic bitonic sort of buf[0..P) in SMEM, P power of 2, all 1024 threads.
__device__ __forceinline__ void bitonic_smem(u64* buf, int P, int tid) {
    for (int ks2 = 2; ks2 <= P; ks2 <<= 1) {
        for (int j = ks2 >> 1; j > 0; j >>= 1) {
            for (int e = tid; e < P; e += 1024) {
                int ixj = e ^ j;
                if (ixj > e) {
                    u64 a = buf[e], bv = buf[ixj];
                    if ((a > bv) == ((e & ks2) == 0)) { buf[e] = bv; buf[ixj] = a; }
                }
            }
            __syncthreads();
        }
    }
}

__device__ __forceinline__ void cswap(u64& a, u64& b, bool asc) {
    if ((a > b) == asc) { u64 t = a; a = b; b = t; }
}

// Register-tiled bitonic sort of 8192 u64 (thread owns 8 contiguous elements;
// all j<=4 substeps run in registers). Same comparison network as bitonic_smem.
__device__ void sort8192(u64* buf, int tid) {
    u64 v[8];
    const int base = tid * 8;
    #pragma unroll
    for (int m = 0; m < 8; m++) v[m] = buf[base + m];
    // ks2=2 (j=1): dir(e) = ((e&2)==0)
    cswap(v[0], v[1], true);  cswap(v[2], v[3], false);
    cswap(v[4], v[5], true);  cswap(v[6], v[7], false);
    // ks2=4 (j=2,1): dir(e) = ((e&4)==0)
    cswap(v[0], v[2], true);  cswap(v[1], v[3], true);
    cswap(v[4], v[6], false); cswap(v[5], v[7], false);
    cswap(v[0], v[1], true);  cswap(v[2], v[3], true);
    cswap(v[4], v[5], false); cswap(v[6], v[7], false);
    // ks2=8 (j=4,2,1): dir constant per 8-block
    {
        bool d = ((base & 8) == 0);
        cswap(v[0], v[4], d); cswap(v[1], v[5], d); cswap(v[2], v[6], d); cswap(v[3], v[7], d);
        cswap(v[0], v[2], d); cswap(v[1], v[3], d); cswap(v[4], v[6], d); cswap(v[5], v[7], d);
        cswap(v[0], v[1], d); cswap(v[2], v[3], d); cswap(v[4], v[5], d); cswap(v[6], v[7], d);
    }
    #pragma unroll
    for (int m = 0; m < 8; m++) buf[base + m] = v[m];
    __syncthreads();

    for (int ks2 = 16; ks2 <= 8192; ks2 <<= 1) {
        for (int j = ks2 >> 1; j >= 8; j >>= 1) {
            #pragma unroll 4
            for (int e = tid; e < 8192; e += 1024) {
                int ixj = e ^ j;
                if (ixj > e) {
                    u64 a = buf[e], bv = buf[ixj];
                    if ((a > bv) == ((e & ks2) == 0)) { buf[e] = bv; buf[ixj] = a; }
                }
            }
            __syncthreads();
        }
        bool d = ((base & ks2) == 0);
        #pragma unroll
        for (int m = 0; m < 8; m++) v[m] = buf[base + m];
        cswap(v[0], v[4], d); cswap(v[1], v[5], d); cswap(v[2], v[6], d); cswap(v[3], v[7], d);
        cswap(v[0], v[2], d); cswap(v[1], v[3], d); cswap(v[4], v[6], d); cswap(v[5], v[7], d);
        cswap(v[0], v[1], d); cswap(v[2], v[3], d); cswap(v[4], v[5], d); cswap(v[6], v[7], d);
        #pragma unroll
        for (int m = 0; m < 8; m++) buf[base + m] = v[m];
        __syncthreads();
    }
}

// ---------------------------------------------------------------------------
// Kernel A: histogram only — read cls coalesced, sigmoid, 14-bit-prefix count.
// ---------------------------------------------------------------------------
__global__ __launch_bounds__(256) void k_hist(Ptrs p) {
    const int lvl = blockIdx.y;
    const int b = blockIdx.z;
    const int N = c_A[lvl] * 80;
    const int base = blockIdx.x * 1024;
    if (base >= N) return;

    const float* cls = p.cls[lvl] + (size_t)b * N;
    u32* hist = g_hist + (b * 5 + lvl) * HBINS;

    #pragma unroll
    for (int t = 0; t < 4; t++) {
        int i = base + t * 256 + threadIdx.x;
        if (i < N) {
            float s = sigm(cls[i]);
            float mv = (s > THR) ? s : -1.0f;
            atomicAdd(&hist[(~ordf(mv)) >> HSHIFT], 1u);
        }
    }
}

// ---------------------------------------------------------------------------
// Kernel B: per (lvl,b) block — bin scan -> boundary; rescan cls (recompute
// sigmoid), gather keys to SMEM; two bitonic sorts; exact decode + emit.
// ---------------------------------------------------------------------------
#define KSEL_SMEM ((BUFB_CAP + 1024) * 8)

__global__ __launch_bounds__(1024) void k_select(Ptrs p) {
    const int lvl = blockIdx.x;
    const int b = blockIdx.y;
    const int tid = threadIdx.x;
    const int lane = tid & 31, wid = tid >> 5;

    const int w = c_w[lvl];
    const int A = c_A[lvl];
    const int N = A * 80;
    const int k = c_k[lvl];
    const int stride = c_stride[lvl];

    const float* cls = p.cls[lvl] + (size_t)b * N;
    u32* hist = g_hist + (b * 5 + lvl) * HBINS;

    extern __shared__ u64 dyn[];
    u64* bufB = dyn;
    u64* bufA = dyn + BUFB_CAP;

    __shared__ u32 s_wsum[32];
    __shared__ int s_B, s_kp;
    __shared__ u32 s_cA, s_cB;

    // 1) scan 16384 bins (16/thread), block exclusive scan, find k-th crossing
    const int b0 = tid * (HBINS / 1024);
    u32 bins[HBINS / 1024];
    u32 st = 0;
    #pragma unroll
    for (int j = 0; j < HBINS / 1024; j++) { bins[j] = hist[b0 + j]; st += bins[j]; }
    u32 incl = st;
    #pragma unroll
    for (int o = 1; o < 32; o <<= 1) {
        u32 v = __shfl_up_sync(0xFFFFFFFFu, incl, o);
        if (lane >= o) incl += v;
    }
    if (lane == 31) s_wsum[wid] = incl;
    __syncthreads();
    if (wid == 0) {
        u32 v = s_wsum[lane];
        #pragma unroll
        for (int o = 1; o < 32; o <<= 1) {
            u32 t2 = __shfl_up_sync(0xFFFFFFFFu, v, o);
            if (lane >= o) v += t2;
        }
        s_wsum[lane] = v;
    }
    __syncthreads();
    u32 myexcl = (wid ? s_wsum[wid - 1] : 0u) + (incl - st);
    if (myexcl < (u32)k && myexcl + st >= (u32)k) {
        u32 cum = myexcl;
        #pragma unroll
        for (int j = 0; j < HBINS / 1024; j++) {
            if (cum + bins[j] >= (u32)k) { s_B = b0 + j; s_kp = k - (int)cum; break; }
            cum += bins[j];
        }
    }
    // re-zero hist for next graph replay
    #pragma unroll
    for (int j = 0; j < HBINS / 1024; j++) hist[b0 + j] = 0;
    if (tid == 0) { s_cA = 0; s_cB = 0; }
    __syncthreads();
    const int B = s_B;
    const int kp = s_kp;

    // 2) gather: recompute sigmoid, prefix<B -> bufA, ==B -> bufB
    for (int i = tid; i < N; i += 1024) {
        float s = sigm(cls[i]);
        float mv = (s > THR) ? s : -1.0f;
        u32 hi = ~ordf(mv);
        int pre = (int)(hi >> HSHIFT);
        if (pre <= B) {
            int c = i / A;
            int anchor = i - c * A;
            u64 key = ((u64)hi << 32) | (u32)(anchor * 80 + c);
            if (pre < B) {
                u32 pos = atomicAdd(&s_cA, 1u);
                bufA[pos] = key;
            } else {
                u32 pos = atomicAdd(&s_cB, 1u);
                if (pos < BUFB_CAP) bufB[pos] = key;
            }
        }
    }
    __syncthreads();
    int nB = (int)min(s_cB, (u32)BUFB_CAP);
    u32 cA = s_cA;

    // 3) sort boundary bin, take smallest kp
    int P = 2;
    while (P < nB) P <<= 1;
    for (int e = tid; e < P; e += 1024) if (e >= nB) bufB[e] = ~0ull;
    __syncthreads();
    bitonic_smem(bufB, P, tid);
    if (tid < kp) bufA[cA + tid] = bufB[tid];
    if (tid >= k) bufA[tid] = ~0ull;
    __syncthreads();

    // 4) final sort of k keys (score desc, idx asc)
    bitonic_smem(bufA, 1024, tid);

    // 5) decode + emit (exact float ops — PROTECT)
    if (tid < k) {
        u64 key = bufA[tid];
        int e = (int)(key & 0xFFFFFFFFull);
        float mv = unordf(~(u32)(key >> 32));
        int anchor = e / 80;
        int lab = e - anchor * 80;
        int y = anchor / w;
        int x = anchor - y * w;
        const float* bb = p.bb[lvl];
        const float* ct = p.ct[lvl];
        float sf = sigm(ct[(size_t)b * A + anchor]);
        float dl = bb[((size_t)b * 4 + 0) * A + anchor];
        float dt = bb[((size_t)b * 4 + 1) * A + anchor];
        float dr = bb[((size_t)b * 4 + 2) * A + anchor];
        float db = bb[((size_t)b * 4 + 3) * A + anchor];
        float px = __fmul_rn(__fadd_rn((float)x, 0.5f), (float)stride);
        float py = __fmul_rn(__fadd_rn((float)y, 0.5f), (float)stride);
        float4 bx;
        bx.x = fminf(fmaxf(__fsub_rn(px, dl), 0.0f), IMGSZ);
        bx.y = fminf(fmaxf(__fsub_rn(py, dt), 0.0f), IMGSZ);
        bx.z = fminf(fmaxf(__fadd_rn(px, dr), 0.0f), IMGSZ);
        bx.w = fminf(fmaxf(__fadd_rn(py, db), 0.0f), IMGSZ);
        bool valid = mv > THR;
        float score = valid ? __fmul_rn(mv, sf) : -1.0f;
        int r = c_outoff[lvl] + tid;          // per-image concat index
        int g = b * KTOT + r;
        g_skey[g] = ((u64)(~ordf(score)) << 32) | (u32)r;
        g_box[g] = bx;
        g_lab[g] = (u8)lab;
        g_valid[g] = valid ? 1 : 0;
    }
}

// ---------------------------------------------------------------------------
// Kernel C: per image — max-coord, register-tiled bitonic argsort (8192),
// write dets/labels, quarter-parallel stable class bucketing, per-class
// greedy NMS (exact decomposition), write keep.
// ---------------------------------------------------------------------------
#define QN 4
#define QSZ (KTOT / QN)          // 1180
#define OFF_ALIVE 75520          // after float4 s_off[4720] (aliases sbuf)
#define OFF_LAB   (OFF_ALIVE + KTOT)
#define OFF_LIST  (OFF_LAB + KTOT)
#define K2_SMEM   (OFF_LIST + KTOT * 2)

__global__ __launch_bounds__(1024) void k_nms(float* __restrict__ out) {
    const int b = blockIdx.x;
    const int tid = threadIdx.x;
    const int K = KTOT;
    const int lane = tid & 31, wid = tid >> 5;

    extern __shared__ unsigned char smraw[];
    u64* sbuf = (u64*)smraw;
    float4* s_off = (float4*)smraw;
    u8* s_alive = smraw + OFF_ALIVE;
    u8* s_lab = smraw + OFF_LAB;
    u16* s_list = (u16*)(smraw + OFF_LIST);

    __shared__ float s_red[32];
    __shared__ float s_maxc;
    __shared__ int s_qcnt[QN * NCLS];    // [q][c]
    __shared__ int s_qofs[NCLS * QN];    // [c][q]
    __shared__ int s_cofs[NCLS], s_ccnt[NCLS];

    // max over all box coords of this image
    const float* bf = (const float*)(g_box + b * K);
    float m = -3.0e38f;
    for (int e = tid; e < K * 4; e += 1024) m = fmaxf(m, bf[e]);
    #pragma unroll
    for (int o = 16; o; o >>= 1) m = fmaxf(m, __shfl_xor_sync(0xFFFFFFFFu, m, o));
    if (lane == 0) s_red[wid] = m;
    if (tid < QN * NCLS) s_qcnt[tid] = 0;
    __syncthreads();
    if (tid == 0) {
        float v = s_red[0];
        for (int i = 1; i < 32; i++) v = fmaxf(v, s_red[i]);
        s_maxc = v;
    }
    __syncthreads();
    float maxc1 = __fadd_rn(s_maxc, 1.0f);

    // keys (score desc, index asc == stable argsort(-scores)), sort
    for (int e = tid; e < 8192; e += 1024)
        sbuf[e] = (e < K) ? g_skey[b * K + e] : ~0ull;
    __syncthreads();
    sort8192(sbuf, tid);

    // stash this thread's rows in registers before s_off aliases sbuf
    int srcs[5];
    float scs[5];
    #pragma unroll
    for (int mrow = 0; mrow < 5; mrow++) {
        int r = tid + mrow * 1024;
        if (r < K) {
            u64 key = sbuf[r];
            srcs[mrow] = (int)(key & 0xFFFFFFFFull);
            scs[mrow] = unordf(~(u32)(key >> 32));
        }
    }
    __syncthreads();

    float* outD = out + (size_t)b * K * 5;
    float* outL = out + (size_t)NB * K * 5 + (size_t)b * K;
    float* outKp = out + (size_t)NB * K * 5 + (size_t)NB * K + (size_t)b * K;

    #pragma unroll
    for (int mrow = 0; mrow < 5; mrow++) {
        int r = tid + mrow * 1024;
        if (r < K) {
            int src = srcs[mrow];
            float4 bx = g_box[b * K + src];
            int lab = g_lab[b * K + src];
            outD[r * 5 + 0] = bx.x;
            outD[r * 5 + 1] = bx.y;
            outD[r * 5 + 2] = bx.z;
            outD[r * 5 + 3] = bx.w;
            outD[r * 5 + 4] = scs[mrow];
            outL[r] = (float)lab;
            float off = __fmul_rn((float)lab, maxc1);
            float4 ob;
            ob.x = __fadd_rn(bx.x, off); ob.y = __fadd_rn(bx.y, off);
            ob.z = __fadd_rn(bx.z, off); ob.w = __fadd_rn(bx.w, off);
            s_off[r] = ob;
            s_alive[r] = g_valid[b * K + src];
            s_lab[r] = (u8)lab;
            atomicAdd(&s_qcnt[(r / QSZ) * NCLS + lab], 1);
        }
    }
    __syncthreads();

    // offsets: class-major, quarters in order within class (stable)
    if (tid == 0) {
        int acc = 0;
        for (int c = 0; c < NCLS; c++) {
            s_cofs[c] = acc;
            for (int q = 0; q < QN; q++) {
                s_qofs[c * QN + q] = acc;
                acc += s_qcnt[q * NCLS + c];
            }
            s_ccnt[c] = acc - s_cofs[c];
        }
    }
    __syncthreads();

    // quarter-parallel stable bucket fill (320 threads: (class, quarter))
    if (tid < NCLS * QN) {
        int c = tid >> 2, q = tid & 3;
        int wpos = s_qofs[c * QN + q];
        int r0 = q * QSZ, r1 = r0 + QSZ;
        for (int r = r0; r < r1; r++)
            if (s_lab[r] == (u8)c) s_list[wpos++] = (u16)r;
    }
    __syncthreads();

    // per-class greedy NMS, one class per warp (exact: cross-class IoU == 0)
    for (int c = wid; c < NCLS; c += 32) {
        int base2 = s_cofs[c];
        int n = s_ccnt[c];
        for (int i = 0; i < n; i++) {
            int ri = s_list[base2 + i];
            if (s_alive[ri]) {
                float4 bi = s_off[ri];
                for (int j = i + 1 + lane; j < n; j += 32) {
                    int rj = s_list[base2 + j];
                    if (s_alive[rj] && suppresses(bi, s_off[rj])) s_alive[rj] = 0;
                }
            }
            __syncwarp();
        }
    }
    __syncthreads();

    for (int r = tid; r < K; r += 1024) outKp[r] = s_alive[r] ? 1.0f : 0.0f;
}

// ---------------------------------------------------------------------------
extern "C" void kernel_launch(void* const* d_in, const int* in_sizes, int n_in,
                              void* d_out, int out_size) {
    (void)n_in; (void)out_size;
    Ptrs p;
    bool interleaved = (in_sizes[1] == 25600);
    for (int i = 0; i < 5; i++) {
        if (interleaved) {
            p.cls[i] = (const float*)d_in[3 * i + 0];
            p.bb[i]  = (const float*)d_in[3 * i + 1];
            p.ct[i]  = (const float*)d_in[3 * i + 2];
        } else {
            p.cls[i] = (const float*)d_in[i];
            p.bb[i]  = (const float*)d_in[5 + i];
            p.ct[i]  = (const float*)d_in[10 + i];
        }
    }
    k_hist<<<dim3(125, 5, NB), 256>>>(p);
    cudaFuncSetAttribute(k_select, cudaFuncAttributeMaxDynamicSharedMemorySize, KSEL_SMEM);
    k_select<<<dim3(5, NB), 1024, KSEL_SMEM>>>(p);
    cudaFuncSetAttribute(k_nms, cudaFuncAttributeMaxDynamicSharedMemorySize, K2_SMEM);
    k_nms<<<NB, 1024, K2_SMEM>>>((float*)d_out);
}

// round 8
// speedup vs baseline: 18.7989x; 1.0411x over previous
#include <cuda_runtime.h>
#include <math.h>

// Problem constants
#define NB 4          // batch
#define KTOT 4720     // concat candidates per image (1000*4 + 720)
#define IMGSZ 320.0f
#define THR 0.025f
#define IOUTHR 0.5f
#define NCLS 80

typedef unsigned long long u64;
typedef unsigned int u32;
typedef unsigned short u16;
typedef unsigned char u8;

// Per-level tables
__device__ __constant__ int   c_w[5]      = {40, 20, 10, 5, 3};
__device__ __constant__ int   c_A[5]      = {1600, 400, 100, 25, 9};
__device__ __constant__ int   c_stride[5] = {8, 16, 32, 64, 128};
__device__ __constant__ int   c_outoff[5] = {0, 1000, 2000, 3000, 4000};
__device__ __constant__ int   c_k[5]      = {1000, 1000, 1000, 1000, 720};

#define NSEG 20
#define HBITS 14
#define HBINS (1 << HBITS)
#define HSHIFT (32 - HBITS)
#define BUF_CAP 8192

// Scratch (static device globals; k_select re-zeros g_hist each call)
__device__ u32           g_hist[NSEG * HBINS];
__device__ u64           g_skey[NB * KTOT];   // (~ordf(final_score)<<32) | per-image index
__device__ float4        g_box[NB * KTOT];
__device__ u8            g_lab[NB * KTOT];
__device__ u8            g_valid[NB * KTOT];

struct Ptrs {
    const float* cls[5];
    const float* bb[5];
    const float* ct[5];
};

__device__ __forceinline__ u32 ordf(float f) {
    u32 u = __float_as_uint(f);
    return (u & 0x80000000u) ? ~u : (u | 0x80000000u);
}
__device__ __forceinline__ float unordf(u32 u) {
    return __uint_as_float((u & 0x80000000u) ? (u & 0x7FFFFFFFu) : ~u);
}

// XLA:CPU f32 exp (Eigen/Cephes pexp) with FMA contraction. PROTECT: bit-exact.
__device__ __forceinline__ float xla_cpu_expf(float x) {
    x = fminf(x,  88.3762626647950f);
    x = fmaxf(x, -88.3762626647949f);
    float fx = floorf(__fmaf_rn(x, 1.44269504088896341f, 0.5f));
    float r = __fmaf_rn(fx, -0.693359375f, x);
    r = __fmaf_rn(fx, 2.12194440e-4f, r);
    float r2 = __fmul_rn(r, r);
    float y = 1.9875691500e-4f;
    y = __fmaf_rn(y, r, 1.3981999507e-3f);
    y = __fmaf_rn(y, r, 8.3334519073e-3f);
    y = __fmaf_rn(y, r, 4.1665795894e-2f);
    y = __fmaf_rn(y, r, 1.6666665459e-1f);
    y = __fmaf_rn(y, r, 5.0000001201e-1f);
    y = __fmaf_rn(y, r2, r);
    y = __fadd_rn(y, 1.0f);
    int n = (int)fx;
    float s = __int_as_float((u32)(n + 127) << 23);
    return __fmul_rn(y, s);
}
__device__ __forceinline__ float sigm(float x) {
    return __fdiv_rn(1.0f, __fadd_rn(1.0f, xla_cpu_expf(-x)));
}

// IoU on offset boxes, exact reference float op order. PROTECT.
__device__ __forceinline__ bool suppresses(const float4 a, const float4 b) {
    float aa = __fmul_rn(__fsub_rn(a.z, a.x), __fsub_rn(a.w, a.y));
    float ab = __fmul_rn(__fsub_rn(b.z, b.x), __fsub_rn(b.w, b.y));
    float ltx = fmaxf(a.x, b.x), lty = fmaxf(a.y, b.y);
    float rbx = fminf(a.z, b.z), rby = fminf(a.w, b.w);
    float w = fmaxf(__fsub_rn(rbx, ltx), 0.0f), h = fmaxf(__fsub_rn(rby, lty), 0.0f);
    float inter = __fmul_rn(w, h);
    float uni = __fsub_rn(__fadd_rn(aa, ab), inter);
    float iou = (uni > 0.0f) ? __fdiv_rn(inter, uni) : 0.0f;
    return iou > IOUTHR;
}

// Generic bitonic sort of buf[0..P) in SMEM, P power of 2, all 1024 threads.
__device__ __forceinline__ void bitonic_smem(u64* buf, int P, int tid) {
    for (int ks2 = 2; ks2 <= P; ks2 <<= 1) {
        for (int j = ks2 >> 1; j > 0; j >>= 1) {
            for (int e = tid; e < P; e += 1024) {
                int ixj = e ^ j;
                if (ixj > e) {
                    u64 a = buf[e], bv = buf[ixj];
                    if ((a > bv) == ((e & ks2) == 0)) { buf[e] = bv; buf[ixj] = a; }
                }
            }
            __syncthreads();
        }
    }
}

__device__ __forceinline__ void cswap(u64& a, u64& b, bool asc) {
    if ((a > b) == asc) { u64 t = a; a = b; b = t; }
}

// Register-tiled bitonic sort of 8192 u64 (thread owns 8 contiguous elements).
__device__ void sort8192(u64* buf, int tid) {
    u64 v[8];
    const int base = tid * 8;
    #pragma unroll
    for (int m = 0; m < 8; m++) v[m] = buf[base + m];
    cswap(v[0], v[1], true);  cswap(v[2], v[3], false);
    cswap(v[4], v[5], true);  cswap(v[6], v[7], false);
    cswap(v[0], v[2], true);  cswap(v[1], v[3], true);
    cswap(v[4], v[6], false); cswap(v[5], v[7], false);
    cswap(v[0], v[1], true);  cswap(v[2], v[3], true);
    cswap(v[4], v[5], false); cswap(v[6], v[7], false);
    {
        bool d = ((base & 8) == 0);
        cswap(v[0], v[4], d); cswap(v[1], v[5], d); cswap(v[2], v[6], d); cswap(v[3], v[7], d);
        cswap(v[0], v[2], d); cswap(v[1], v[3], d); cswap(v[4], v[6], d); cswap(v[5], v[7], d);
        cswap(v[0], v[1], d); cswap(v[2], v[3], d); cswap(v[4], v[5], d); cswap(v[6], v[7], d);
    }
    #pragma unroll
    for (int m = 0; m < 8; m++) buf[base + m] = v[m];
    __syncthreads();

    for (int ks2 = 16; ks2 <= 8192; ks2 <<= 1) {
        for (int j = ks2 >> 1; j >= 8; j >>= 1) {
            #pragma unroll 4
            for (int e = tid; e < 8192; e += 1024) {
                int ixj = e ^ j;
                if (ixj > e) {
                    u64 a = buf[e], bv = buf[ixj];
                    if ((a > bv) == ((e & ks2) == 0)) { buf[e] = bv; buf[ixj] = a; }
                }
            }
            __syncthreads();
        }
        bool d = ((base & ks2) == 0);
        #pragma unroll
        for (int m = 0; m < 8; m++) v[m] = buf[base + m];
        cswap(v[0], v[4], d); cswap(v[1], v[5], d); cswap(v[2], v[6], d); cswap(v[3], v[7], d);
        cswap(v[0], v[2], d); cswap(v[1], v[3], d); cswap(v[4], v[6], d); cswap(v[5], v[7], d);
        cswap(v[0], v[1], d); cswap(v[2], v[3], d); cswap(v[4], v[5], d); cswap(v[6], v[7], d);
        #pragma unroll
        for (int m = 0; m < 8; m++) buf[base + m] = v[m];
        __syncthreads();
    }
}

// ---------------------------------------------------------------------------
// Kernel A: LOGIT-ordinal histogram (no sigmoid). float4 loads.
// Monotonicity of sigm means logit-ordinal bracketing selects the same top-k
// superset; score-level ties span <=~30 ordinals << 2^18 bin span.
// ---------------------------------------------------------------------------
__global__ __launch_bounds__(256) void k_hist(Ptrs p) {
    const int lvl = blockIdx.y;
    const int b = blockIdx.z;
    const int N = c_A[lvl] * 80;       // all N divisible by 4
    const int i4 = blockIdx.x * 256 + threadIdx.x;
    if (i4 * 4 >= N) return;

    const float4* cls4 = (const float4*)(p.cls[lvl] + (size_t)b * N);
    u32* hist = g_hist + (b * 5 + lvl) * HBINS;

    float4 v = cls4[i4];
    atomicAdd(&hist[(~ordf(v.x)) >> HSHIFT], 1u);
    atomicAdd(&hist[(~ordf(v.y)) >> HSHIFT], 1u);
    atomicAdd(&hist[(~ordf(v.z)) >> HSHIFT], 1u);
    atomicAdd(&hist[(~ordf(v.w)) >> HSHIFT], 1u);
}

// ---------------------------------------------------------------------------
// Kernel B: per (lvl,b) block — logit-bin scan -> boundary B; gather all
// elements with logit-prefix <= B+1 (guard bin covers all score ties),
// compute exact score keys only for gathered; one bitonic sort; take top-k;
// exact decode + emit.
// ---------------------------------------------------------------------------
#define KSEL_SMEM (BUF_CAP * 8)

__global__ __launch_bounds__(1024) void k_select(Ptrs p) {
    const int lvl = blockIdx.x;
    const int b = blockIdx.y;
    const int tid = threadIdx.x;
    const int lane = tid & 31, wid = tid >> 5;

    const int w = c_w[lvl];
    const int A = c_A[lvl];
    const int N = A * 80;
    const int k = c_k[lvl];
    const int stride = c_stride[lvl];

    const float* cls = p.cls[lvl] + (size_t)b * N;
    u32* hist = g_hist + (b * 5 + lvl) * HBINS;

    extern __shared__ u64 buf[];   // BUF_CAP

    __shared__ u32 s_wsum[32];
    __shared__ int s_B;
    __shared__ u32 s_cnt;

    // 1) scan 16384 bins (16/thread), block exclusive scan, find k-th crossing
    const int b0 = tid * (HBINS / 1024);
    u32 bins[HBINS / 1024];
    u32 st = 0;
    #pragma unroll
    for (int j = 0; j < HBINS / 1024; j++) { bins[j] = hist[b0 + j]; st += bins[j]; }
    u32 incl = st;
    #pragma unroll
    for (int o = 1; o < 32; o <<= 1) {
        u32 v = __shfl_up_sync(0xFFFFFFFFu, incl, o);
        if (lane >= o) incl += v;
    }
    if (lane == 31) s_wsum[wid] = incl;
    __syncthreads();
    if (wid == 0) {
        u32 v = s_wsum[lane];
        #pragma unroll
        for (int o = 1; o < 32; o <<= 1) {
            u32 t2 = __shfl_up_sync(0xFFFFFFFFu, v, o);
            if (lane >= o) v += t2;
        }
        s_wsum[lane] = v;
    }
    __syncthreads();
    u32 myexcl = (wid ? s_wsum[wid - 1] : 0u) + (incl - st);
    if (myexcl < (u32)k && myexcl + st >= (u32)k) {
        u32 cum = myexcl;
        #pragma unroll
        for (int j = 0; j < HBINS / 1024; j++) {
            if (cum + bins[j] >= (u32)k) { s_B = b0 + j; break; }
            cum += bins[j];
        }
    }
    // re-zero hist for next graph replay
    #pragma unroll
    for (int j = 0; j < HBINS / 1024; j++) hist[b0 + j] = 0;
    if (tid == 0) s_cnt = 0;
    __syncthreads();
    const u32 Bg = (u32)s_B + 1;   // guard bin included

    // 2) gather: cheap logit-prefix cull; exact score key only for survivors
    for (int i = tid; i < N; i += 1024) {
        float x = cls[i];
        u32 pl = (~ordf(x)) >> HSHIFT;
        if (pl <= Bg) {
            float s = sigm(x);
            float mv = (s > THR) ? s : -1.0f;
            int c = i / A;
            int anchor = i - c * A;
            u64 key = ((u64)(~ordf(mv)) << 32) | (u32)(anchor * 80 + c);
            u32 pos = atomicAdd(&s_cnt, 1u);
            if (pos < BUF_CAP) buf[pos] = key;
        }
    }
    __syncthreads();
    int nG = (int)min(s_cnt, (u32)BUF_CAP);

    // 3) pad to power of 2, sort ascending (== score desc, idx asc)
    int P = 2;
    while (P < nG) P <<= 1;
    if (P < 1024) P = 1024;
    for (int e = tid; e < P; e += 1024) if (e >= nG) buf[e] = ~0ull;
    __syncthreads();
    bitonic_smem(buf, P, tid);

    // 4) decode + emit top-k (exact float ops — PROTECT)
    if (tid < k) {
        u64 key = buf[tid];
        int e = (int)(key & 0xFFFFFFFFull);
        float mv = unordf(~(u32)(key >> 32));
        int anchor = e / 80;
        int lab = e - anchor * 80;
        int y = anchor / w;
        int x = anchor - y * w;
        const float* bb = p.bb[lvl];
        const float* ct = p.ct[lvl];
        float sf = sigm(ct[(size_t)b * A + anchor]);
        float dl = bb[((size_t)b * 4 + 0) * A + anchor];
        float dt = bb[((size_t)b * 4 + 1) * A + anchor];
        float dr = bb[((size_t)b * 4 + 2) * A + anchor];
        float db = bb[((size_t)b * 4 + 3) * A + anchor];
        float px = __fmul_rn(__fadd_rn((float)x, 0.5f), (float)stride);
        float py = __fmul_rn(__fadd_rn((float)y, 0.5f), (float)stride);
        float4 bx;
        bx.x = fminf(fmaxf(__fsub_rn(px, dl), 0.0f), IMGSZ);
        bx.y = fminf(fmaxf(__fsub_rn(py, dt), 0.0f), IMGSZ);
        bx.z = fminf(fmaxf(__fadd_rn(px, dr), 0.0f), IMGSZ);
        bx.w = fminf(fmaxf(__fadd_rn(py, db), 0.0f), IMGSZ);
        bool valid = mv > THR;
        float score = valid ? __fmul_rn(mv, sf) : -1.0f;
        int r = c_outoff[lvl] + tid;
        int g = b * KTOT + r;
        g_skey[g] = ((u64)(~ordf(score)) << 32) | (u32)r;
        g_box[g] = bx;
        g_lab[g] = (u8)lab;
        g_valid[g] = valid ? 1 : 0;
    }
}

// ---------------------------------------------------------------------------
// Kernel C: per image — max-coord, register-tiled bitonic argsort (8192),
// write dets/labels, quarter-parallel stable class bucketing, per-class
// greedy NMS (exact decomposition), write keep.
// ---------------------------------------------------------------------------
#define QN 4
#define QSZ (KTOT / QN)          // 1180
#define OFF_ALIVE 75520          // after float4 s_off[4720] (aliases sbuf)
#define OFF_LAB   (OFF_ALIVE + KTOT)
#define OFF_LIST  (OFF_LAB + KTOT)
#define K2_SMEM   (OFF_LIST + KTOT * 2)

__global__ __launch_bounds__(1024) void k_nms(float* __restrict__ out) {
    const int b = blockIdx.x;
    const int tid = threadIdx.x;
    const int K = KTOT;
    const int lane = tid & 31, wid = tid >> 5;

    extern __shared__ unsigned char smraw[];
    u64* sbuf = (u64*)smraw;
    float4* s_off = (float4*)smraw;
    u8* s_alive = smraw + OFF_ALIVE;
    u8* s_lab = smraw + OFF_LAB;
    u16* s_list = (u16*)(smraw + OFF_LIST);

    __shared__ float s_red[32];
    __shared__ float s_maxc;
    __shared__ int s_qcnt[QN * NCLS];    // [q][c]
    __shared__ int s_qofs[NCLS * QN];    // [c][q]
    __shared__ int s_cofs[NCLS], s_ccnt[NCLS];

    const float* bf = (const float*)(g_box + b * K);
    float m = -3.0e38f;
    for (int e = tid; e < K * 4; e += 1024) m = fmaxf(m, bf[e]);
    #pragma unroll
    for (int o = 16; o; o >>= 1) m = fmaxf(m, __shfl_xor_sync(0xFFFFFFFFu, m, o));
    if (lane == 0) s_red[wid] = m;
    if (tid < QN * NCLS) s_qcnt[tid] = 0;
    __syncthreads();
    if (tid == 0) {
        float v = s_red[0];
        for (int i = 1; i < 32; i++) v = fmaxf(v, s_red[i]);
        s_maxc = v;
    }
    __syncthreads();
    float maxc1 = __fadd_rn(s_maxc, 1.0f);

    for (int e = tid; e < 8192; e += 1024)
        sbuf[e] = (e < K) ? g_skey[b * K + e] : ~0ull;
    __syncthreads();
    sort8192(sbuf, tid);

    int srcs[5];
    float scs[5];
    #pragma unroll
    for (int mrow = 0; mrow < 5; mrow++) {
        int r = tid + mrow * 1024;
        if (r < K) {
            u64 key = sbuf[r];
            srcs[mrow] = (int)(key & 0xFFFFFFFFull);
            scs[mrow] = unordf(~(u32)(key >> 32));
        }
    }
    __syncthreads();

    float* outD = out + (size_t)b * K * 5;
    float* outL = out + (size_t)NB * K * 5 + (size_t)b * K;
    float* outKp = out + (size_t)NB * K * 5 + (size_t)NB * K + (size_t)b * K;

    #pragma unroll
    for (int mrow = 0; mrow < 5; mrow++) {
        int r = tid + mrow * 1024;
        if (r < K) {
            int src = srcs[mrow];
            float4 bx = g_box[b * K + src];
            int lab = g_lab[b * K + src];
            outD[r * 5 + 0] = bx.x;
            outD[r * 5 + 1] = bx.y;
            outD[r * 5 + 2] = bx.z;
            outD[r * 5 + 3] = bx.w;
            outD[r * 5 + 4] = scs[mrow];
            outL[r] = (float)lab;
            float off = __fmul_rn((float)lab, maxc1);
            float4 ob;
            ob.x = __fadd_rn(bx.x, off); ob.y = __fadd_rn(bx.y, off);
            ob.z = __fadd_rn(bx.z, off); ob.w = __fadd_rn(bx.w, off);
            s_off[r] = ob;
            s_alive[r] = g_valid[b * K + src];
            s_lab[r] = (u8)lab;
            atomicAdd(&s_qcnt[(r / QSZ) * NCLS + lab], 1);
        }
    }
    __syncthreads();

    if (tid == 0) {
        int acc = 0;
        for (int c = 0; c < NCLS; c++) {
            s_cofs[c] = acc;
            for (int q = 0; q < QN; q++) {
                s_qofs[c * QN + q] = acc;
                acc += s_qcnt[q * NCLS + c];
            }
            s_ccnt[c] = acc - s_cofs[c];
        }
    }
    __syncthreads();

    if (tid < NCLS * QN) {
        int c = tid >> 2, q = tid & 3;
        int wpos = s_qofs[c * QN + q];
        int r0 = q * QSZ, r1 = r0 + QSZ;
        for (int r = r0; r < r1; r++)
            if (s_lab[r] == (u8)c) s_list[wpos++] = (u16)r;
    }
    __syncthreads();

    for (int c = wid; c < NCLS; c += 32) {
        int base2 = s_cofs[c];
        int n = s_ccnt[c];
        for (int i = 0; i < n; i++) {
            int ri = s_list[base2 + i];
            if (s_alive[ri]) {
                float4 bi = s_off[ri];
                for (int j = i + 1 + lane; j < n; j += 32) {
                    int rj = s_list[base2 + j];
                    if (s_alive[rj] && suppresses(bi, s_off[rj])) s_alive[rj] = 0;
                }
            }
            __syncwarp();
        }
    }
    __syncthreads();

    for (int r = tid; r < K; r += 1024) outKp[r] = s_alive[r] ? 1.0f : 0.0f;
}

// ---------------------------------------------------------------------------
extern "C" void kernel_launch(void* const* d_in, const int* in_sizes, int n_in,
                              void* d_out, int out_size) {
    (void)n_in; (void)out_size;
    Ptrs p;
    bool interleaved = (in_sizes[1] == 25600);
    for (int i = 0; i < 5; i++) {
        if (interleaved) {
            p.cls[i] = (const float*)d_in[3 * i + 0];
            p.bb[i]  = (const float*)d_in[3 * i + 1];
            p.ct[i]  = (const float*)d_in[3 * i + 2];
        } else {
            p.cls[i] = (const float*)d_in[i];
            p.bb[i]  = (const float*)d_in[5 + i];
            p.ct[i]  = (const float*)d_in[10 + i];
        }
    }
    k_hist<<<dim3(125, 5, NB), 256>>>(p);
    cudaFuncSetAttribute(k_select, cudaFuncAttributeMaxDynamicSharedMemorySize, KSEL_SMEM);
    k_select<<<dim3(5, NB), 1024, KSEL_SMEM>>>(p);
    cudaFuncSetAttribute(k_nms, cudaFuncAttributeMaxDynamicSharedMemorySize, K2_SMEM);
    k_nms<<<NB, 1024, K2_SMEM>>>((float*)d_out);
}

// round 9
// speedup vs baseline: 23.8455x; 1.2685x over previous
#include <cuda_runtime.h>
#include <math.h>

// Problem constants
#define NB 4          // batch
#define KTOT 4720     // concat candidates per image (1000*4 + 720)
#define IMGSZ 320.0f
#define THR 0.025f
#define IOUTHR 0.5f
#define NCLS 80

typedef unsigned long long u64;
typedef unsigned int u32;
typedef unsigned short u16;
typedef unsigned char u8;

// Per-level tables
__device__ __constant__ int   c_w[5]      = {40, 20, 10, 5, 3};
__device__ __constant__ int   c_A[5]      = {1600, 400, 100, 25, 9};
__device__ __constant__ int   c_stride[5] = {8, 16, 32, 64, 128};
__device__ __constant__ int   c_outoff[5] = {0, 1000, 2000, 3000, 4000};
__device__ __constant__ int   c_k[5]      = {1000, 1000, 1000, 1000, 720};

#define HBITS 13
#define HBINS (1 << HBITS)
#define HSHIFT (32 - HBITS)
#define BUF_CAP 8192

// Scratch (static device globals)
__device__ u64           g_skey[NB * KTOT];   // per-level segments sorted by final-score key
__device__ float4        g_box[NB * KTOT];    // indexed by concat position r
__device__ u8            g_lab[NB * KTOT];
__device__ u8            g_valid[NB * KTOT];

struct Ptrs {
    const float* cls[5];
    const float* bb[5];
    const float* ct[5];
};

__device__ __forceinline__ u32 ordf(float f) {
    u32 u = __float_as_uint(f);
    return (u & 0x80000000u) ? ~u : (u | 0x80000000u);
}
__device__ __forceinline__ float unordf(u32 u) {
    return __uint_as_float((u & 0x80000000u) ? (u & 0x7FFFFFFFu) : ~u);
}

// XLA:CPU f32 exp (Eigen/Cephes pexp) with FMA contraction. PROTECT: bit-exact.
__device__ __forceinline__ float xla_cpu_expf(float x) {
    x = fminf(x,  88.3762626647950f);
    x = fmaxf(x, -88.3762626647949f);
    float fx = floorf(__fmaf_rn(x, 1.44269504088896341f, 0.5f));
    float r = __fmaf_rn(fx, -0.693359375f, x);
    r = __fmaf_rn(fx, 2.12194440e-4f, r);
    float r2 = __fmul_rn(r, r);
    float y = 1.9875691500e-4f;
    y = __fmaf_rn(y, r, 1.3981999507e-3f);
    y = __fmaf_rn(y, r, 8.3334519073e-3f);
    y = __fmaf_rn(y, r, 4.1665795894e-2f);
    y = __fmaf_rn(y, r, 1.6666665459e-1f);
    y = __fmaf_rn(y, r, 5.0000001201e-1f);
    y = __fmaf_rn(y, r2, r);
    y = __fadd_rn(y, 1.0f);
    int n = (int)fx;
    float s = __int_as_float((u32)(n + 127) << 23);
    return __fmul_rn(y, s);
}
__device__ __forceinline__ float sigm(float x) {
    return __fdiv_rn(1.0f, __fadd_rn(1.0f, xla_cpu_expf(-x)));
}

// IoU on offset boxes, exact reference float op order. PROTECT.
__device__ __forceinline__ bool suppresses(const float4 a, const float4 b) {
    float aa = __fmul_rn(__fsub_rn(a.z, a.x), __fsub_rn(a.w, a.y));
    float ab = __fmul_rn(__fsub_rn(b.z, b.x), __fsub_rn(b.w, b.y));
    float ltx = fmaxf(a.x, b.x), lty = fmaxf(a.y, b.y);
    float rbx = fminf(a.z, b.z), rby = fminf(a.w, b.w);
    float w = fmaxf(__fsub_rn(rbx, ltx), 0.0f), h = fmaxf(__fsub_rn(rby, lty), 0.0f);
    float inter = __fmul_rn(w, h);
    float uni = __fsub_rn(__fadd_rn(aa, ab), inter);
    float iou = (uni > 0.0f) ? __fdiv_rn(inter, uni) : 0.0f;
    return iou > IOUTHR;
}

// Generic bitonic sort of buf[0..P) in SMEM, P power of 2, all 1024 threads.
__device__ __forceinline__ void bitonic_smem(u64* buf, int P, int tid) {
    for (int ks2 = 2; ks2 <= P; ks2 <<= 1) {
        for (int j = ks2 >> 1; j > 0; j >>= 1) {
            for (int e = tid; e < P; e += 1024) {
                int ixj = e ^ j;
                if (ixj > e) {
                    u64 a = buf[e], bv = buf[ixj];
                    if ((a > bv) == ((e & ks2) == 0)) { buf[e] = bv; buf[ixj] = a; }
                }
            }
            __syncthreads();
        }
    }
}

__device__ __forceinline__ void cswap(u64& a, u64& b, bool asc) {
    if ((a > b) == asc) { u64 t = a; a = b; b = t; }
}

// Bitonic stages of an 8192-element network starting at stage first_ks2
// (register-tiled: j<=4 substeps run in regs; thread owns 8 contiguous elems).
// Precondition for first_ks2 = 2048: each 1024-run sorted, alternating asc/desc.
__device__ void bitonic_stages8192(u64* buf, int tid, int first_ks2) {
    const int base = tid * 8;
    u64 v[8];
    for (int ks2 = first_ks2; ks2 <= 8192; ks2 <<= 1) {
        for (int j = ks2 >> 1; j >= 8; j >>= 1) {
            #pragma unroll 4
            for (int e = tid; e < 8192; e += 1024) {
                int ixj = e ^ j;
                if (ixj > e) {
                    u64 a = buf[e], bv = buf[ixj];
                    if ((a > bv) == ((e & ks2) == 0)) { buf[e] = bv; buf[ixj] = a; }
                }
            }
            __syncthreads();
        }
        bool d = ((base & ks2) == 0);
        #pragma unroll
        for (int m = 0; m < 8; m++) v[m] = buf[base + m];
        cswap(v[0], v[4], d); cswap(v[1], v[5], d); cswap(v[2], v[6], d); cswap(v[3], v[7], d);
        cswap(v[0], v[2], d); cswap(v[1], v[3], d); cswap(v[4], v[6], d); cswap(v[5], v[7], d);
        cswap(v[0], v[1], d); cswap(v[2], v[3], d); cswap(v[4], v[5], d); cswap(v[6], v[7], d);
        #pragma unroll
        for (int m = 0; m < 8; m++) buf[base + m] = v[m];
        __syncthreads();
    }
}

// ---------------------------------------------------------------------------
// Kernel 1: per (lvl,b) block — fused histogram + select.
//   pass1: float4 cls reads -> privatized SMEM logit-ordinal histogram
//   scan bins -> boundary B; pass2: L2-hot rescan, cull prefix<=B+1 (guard
//   bin covers all score ties), exact score keys for survivors; bitonic sort;
//   top-k decode; per-level final-score sort; emit sorted g_skey segment.
// smem: hist u32[8192] (32KB) | buf u64[8192] (64KB) | fin u64[1024] (8KB)
// ---------------------------------------------------------------------------
#define SEL_H_OFF 0
#define SEL_B_OFF 32768
#define SEL_F_OFF (32768 + 65536)
#define KSEL_SMEM (SEL_F_OFF + 8192)

__global__ __launch_bounds__(1024) void k_sel(Ptrs p) {
    const int lvl = blockIdx.x;
    const int b = blockIdx.y;
    const int tid = threadIdx.x;
    const int lane = tid & 31, wid = tid >> 5;

    const int w = c_w[lvl];
    const int A = c_A[lvl];
    const int N = A * 80;
    const int k = c_k[lvl];
    const int stride = c_stride[lvl];

    const float* cls = p.cls[lvl] + (size_t)b * N;

    extern __shared__ unsigned char smraw[];
    u32* hist = (u32*)(smraw + SEL_H_OFF);
    u64* buf = (u64*)(smraw + SEL_B_OFF);
    u64* fin = (u64*)(smraw + SEL_F_OFF);

    __shared__ u32 s_wsum[32];
    __shared__ int s_B;
    __shared__ u32 s_cnt;

    // zero hist
    #pragma unroll
    for (int i = tid; i < HBINS; i += 1024) hist[i] = 0;
    __syncthreads();

    // pass1: logit-ordinal histogram (no sigmoid), float4 loads
    const float4* cls4 = (const float4*)cls;
    const int N4 = N >> 2;
    for (int i = tid; i < N4; i += 1024) {
        float4 v = cls4[i];
        atomicAdd(&hist[(~ordf(v.x)) >> HSHIFT], 1u);
        atomicAdd(&hist[(~ordf(v.y)) >> HSHIFT], 1u);
        atomicAdd(&hist[(~ordf(v.z)) >> HSHIFT], 1u);
        atomicAdd(&hist[(~ordf(v.w)) >> HSHIFT], 1u);
    }
    __syncthreads();

    // scan 8192 bins (8/thread), block exclusive scan, find k-th crossing
    const int b0 = tid * (HBINS / 1024);
    u32 bins[HBINS / 1024];
    u32 st = 0;
    #pragma unroll
    for (int j = 0; j < HBINS / 1024; j++) { bins[j] = hist[b0 + j]; st += bins[j]; }
    u32 incl = st;
    #pragma unroll
    for (int o = 1; o < 32; o <<= 1) {
        u32 v = __shfl_up_sync(0xFFFFFFFFu, incl, o);
        if (lane >= o) incl += v;
    }
    if (lane == 31) s_wsum[wid] = incl;
    __syncthreads();
    if (wid == 0) {
        u32 v = s_wsum[lane];
        #pragma unroll
        for (int o = 1; o < 32; o <<= 1) {
            u32 t2 = __shfl_up_sync(0xFFFFFFFFu, v, o);
            if (lane >= o) v += t2;
        }
        s_wsum[lane] = v;
    }
    __syncthreads();
    u32 myexcl = (wid ? s_wsum[wid - 1] : 0u) + (incl - st);
    if (myexcl < (u32)k && myexcl + st >= (u32)k) {
        u32 cum = myexcl;
        #pragma unroll
        for (int j = 0; j < HBINS / 1024; j++) {
            if (cum + bins[j] >= (u32)k) { s_B = b0 + j; break; }
            cum += bins[j];
        }
    }
    if (tid == 0) s_cnt = 0;
    __syncthreads();
    const u32 Bg = (u32)s_B + 1;   // guard bin included

    // pass2: gather (cheap logit-prefix cull; exact score key for survivors)
    for (int i = tid; i < N; i += 1024) {
        float x = cls[i];
        u32 pl = (~ordf(x)) >> HSHIFT;
        if (pl <= Bg) {
            float s = sigm(x);
            float mv = (s > THR) ? s : -1.0f;
            int c = i / A;
            int anchor = i - c * A;
            u64 key = ((u64)(~ordf(mv)) << 32) | (u32)(anchor * 80 + c);
            u32 pos = atomicAdd(&s_cnt, 1u);
            if (pos < BUF_CAP) buf[pos] = key;
        }
    }
    __syncthreads();
    int nG = (int)min(s_cnt, (u32)BUF_CAP);

    // sort ascending (== mv desc, idx asc)
    int P = 2;
    while (P < nG) P <<= 1;
    if (P < 1024) P = 1024;
    for (int e = tid; e < P; e += 1024) if (e >= nG) buf[e] = ~0ull;
    __syncthreads();
    bitonic_smem(buf, P, tid);

    // decode + emit top-k (exact float ops — PROTECT); build final-score keys
    u64 fkey = ~0ull;
    if (tid < k) {
        u64 key = buf[tid];
        int e = (int)(key & 0xFFFFFFFFull);
        float mv = unordf(~(u32)(key >> 32));
        int anchor = e / 80;
        int lab = e - anchor * 80;
        int y = anchor / w;
        int x = anchor - y * w;
        const float* bb = p.bb[lvl];
        const float* ct = p.ct[lvl];
        float sf = sigm(ct[(size_t)b * A + anchor]);
        float dl = bb[((size_t)b * 4 + 0) * A + anchor];
        float dt = bb[((size_t)b * 4 + 1) * A + anchor];
        float dr = bb[((size_t)b * 4 + 2) * A + anchor];
        float db = bb[((size_t)b * 4 + 3) * A + anchor];
        float px = __fmul_rn(__fadd_rn((float)x, 0.5f), (float)stride);
        float py = __fmul_rn(__fadd_rn((float)y, 0.5f), (float)stride);
        float4 bx;
        bx.x = fminf(fmaxf(__fsub_rn(px, dl), 0.0f), IMGSZ);
        bx.y = fminf(fmaxf(__fsub_rn(py, dt), 0.0f), IMGSZ);
        bx.z = fminf(fmaxf(__fadd_rn(px, dr), 0.0f), IMGSZ);
        bx.w = fminf(fmaxf(__fadd_rn(py, db), 0.0f), IMGSZ);
        bool valid = mv > THR;
        float score = valid ? __fmul_rn(mv, sf) : -1.0f;
        int r = c_outoff[lvl] + tid;    // reference concat position
        int g = b * KTOT + r;
        g_box[g] = bx;
        g_lab[g] = (u8)lab;
        g_valid[g] = valid ? 1 : 0;
        fkey = ((u64)(~ordf(score)) << 32) | (u32)r;
    }
    fin[tid] = fkey;
    __syncthreads();

    // per-level sort by final-score key (stable via unique r in low bits)
    bitonic_smem(fin, 1024, tid);
    if (tid < k) g_skey[b * KTOT + c_outoff[lvl] + tid] = fin[tid];
}

// ---------------------------------------------------------------------------
// Kernel 2: per image — load 5 pre-sorted segments in alternating asc/desc
// 1024-slot arrangement, run only bitonic stages 2048/4096/8192 (36 substeps),
// write dets/labels, quarter-parallel class bucketing, per-class greedy NMS.
// ---------------------------------------------------------------------------
#define QN 4
#define QSZ (KTOT / QN)          // 1180
#define OFF_ALIVE 75520          // after float4 s_off[4720] (aliases sbuf)
#define OFF_LAB   (OFF_ALIVE + KTOT)
#define OFF_LIST  (OFF_LAB + KTOT)
#define K2_SMEM   (OFF_LIST + KTOT * 2)

__global__ __launch_bounds__(1024) void k_nms(float* __restrict__ out) {
    const int b = blockIdx.x;
    const int tid = threadIdx.x;
    const int K = KTOT;
    const int lane = tid & 31, wid = tid >> 5;

    extern __shared__ unsigned char smraw[];
    u64* sbuf = (u64*)smraw;
    float4* s_off = (float4*)smraw;
    u8* s_alive = smraw + OFF_ALIVE;
    u8* s_lab = smraw + OFF_LAB;
    u16* s_list = (u16*)(smraw + OFF_LIST);

    __shared__ float s_red[32];
    __shared__ float s_maxc;
    __shared__ int s_qcnt[QN * NCLS];
    __shared__ int s_qofs[NCLS * QN];
    __shared__ int s_cofs[NCLS], s_ccnt[NCLS];

    // max over all box coords of this image
    const float* bf = (const float*)(g_box + b * K);
    float m = -3.0e38f;
    for (int e = tid; e < K * 4; e += 1024) m = fmaxf(m, bf[e]);
    #pragma unroll
    for (int o = 16; o; o >>= 1) m = fmaxf(m, __shfl_xor_sync(0xFFFFFFFFu, m, o));
    if (lane == 0) s_red[wid] = m;
    if (tid < QN * NCLS) s_qcnt[tid] = 0;
    __syncthreads();
    if (tid == 0) {
        float v = s_red[0];
        for (int i = 1; i < 32; i++) v = fmaxf(v, s_red[i]);
        s_maxc = v;
    }
    __syncthreads();
    float maxc1 = __fadd_rn(s_maxc, 1.0f);

    // arrangement: slot l = [l*1024,(l+1)*1024): even -> segment ascending,
    // pads (MAX) at end; odd -> pads first then segment reversed (descending).
    // slots 5..7 all MAX. This satisfies the precondition of stage ks2=2048.
    {
        const u64* sk = g_skey + b * K;
        #pragma unroll
        for (int mrow = 0; mrow < 8; mrow++) {
            int e = tid + mrow * 1024;
            int l = e >> 10, j = e & 1023;
            u64 key = ~0ull;
            if (l < 5) {
                int off = c_outoff[l];
                int len = c_k[l];
                if ((l & 1) == 0) {
                    if (j < len) key = sk[off + j];
                } else {
                    int pad = 1024 - len;
                    if (j >= pad) key = sk[off + (1023 - j)];
                }
            }
            sbuf[e] = key;
        }
    }
    __syncthreads();
    bitonic_stages8192(sbuf, tid, 2048);

    // stash rows in registers before s_off aliases sbuf
    int srcs[5];
    float scs[5];
    #pragma unroll
    for (int mrow = 0; mrow < 5; mrow++) {
        int r = tid + mrow * 1024;
        if (r < K) {
            u64 key = sbuf[r];
            srcs[mrow] = (int)(key & 0xFFFFFFFFull);
            scs[mrow] = unordf(~(u32)(key >> 32));
        }
    }
    __syncthreads();

    float* outD = out + (size_t)b * K * 5;
    float* outL = out + (size_t)NB * K * 5 + (size_t)b * K;
    float* outKp = out + (size_t)NB * K * 5 + (size_t)NB * K + (size_t)b * K;

    #pragma unroll
    for (int mrow = 0; mrow < 5; mrow++) {
        int r = tid + mrow * 1024;
        if (r < K) {
            int src = srcs[mrow];
            float4 bx = g_box[b * K + src];
            int lab = g_lab[b * K + src];
            outD[r * 5 + 0] = bx.x;
            outD[r * 5 + 1] = bx.y;
            outD[r * 5 + 2] = bx.z;
            outD[r * 5 + 3] = bx.w;
            outD[r * 5 + 4] = scs[mrow];
            outL[r] = (float)lab;
            float off = __fmul_rn((float)lab, maxc1);
            float4 ob;
            ob.x = __fadd_rn(bx.x, off); ob.y = __fadd_rn(bx.y, off);
            ob.z = __fadd_rn(bx.z, off); ob.w = __fadd_rn(bx.w, off);
            s_off[r] = ob;
            s_alive[r] = g_valid[b * K + src];
            s_lab[r] = (u8)lab;
            atomicAdd(&s_qcnt[(r / QSZ) * NCLS + lab], 1);
        }
    }
    __syncthreads();

    if (tid == 0) {
        int acc = 0;
        for (int c = 0; c < NCLS; c++) {
            s_cofs[c] = acc;
            for (int q = 0; q < QN; q++) {
                s_qofs[c * QN + q] = acc;
                acc += s_qcnt[q * NCLS + c];
            }
            s_ccnt[c] = acc - s_cofs[c];
        }
    }
    __syncthreads();

    if (tid < NCLS * QN) {
        int c = tid >> 2, q = tid & 3;
        int wpos = s_qofs[c * QN + q];
        int r0 = q * QSZ, r1 = r0 + QSZ;
        for (int r = r0; r < r1; r++)
            if (s_lab[r] == (u8)c) s_list[wpos++] = (u16)r;
    }
    __syncthreads();

    // per-class greedy NMS, one class per warp (exact: cross-class IoU == 0)
    for (int c = wid; c < NCLS; c += 32) {
        int base2 = s_cofs[c];
        int n = s_ccnt[c];
        for (int i = 0; i < n; i++) {
            int ri = s_list[base2 + i];
            if (s_alive[ri]) {
                float4 bi = s_off[ri];
                for (int j = i + 1 + lane; j < n; j += 32) {
                    int rj = s_list[base2 + j];
                    if (s_alive[rj] && suppresses(bi, s_off[rj])) s_alive[rj] = 0;
                }
            }
            __syncwarp();
        }
    }
    __syncthreads();

    for (int r = tid; r < K; r += 1024) outKp[r] = s_alive[r] ? 1.0f : 0.0f;
}

// ---------------------------------------------------------------------------
extern "C" void kernel_launch(void* const* d_in, const int* in_sizes, int n_in,
                              void* d_out, int out_size) {
    (void)n_in; (void)out_size;
    Ptrs p;
    bool interleaved = (in_sizes[1] == 25600);
    for (int i = 0; i < 5; i++) {
        if (interleaved) {
            p.cls[i] = (const float*)d_in[3 * i + 0];
            p.bb[i]  = (const float*)d_in[3 * i + 1];
            p.ct[i]  = (const float*)d_in[3 * i + 2];
        } else {
            p.cls[i] = (const float*)d_in[i];
            p.bb[i]  = (const float*)d_in[5 + i];
            p.ct[i]  = (const float*)d_in[10 + i];
        }
    }
    cudaFuncSetAttribute(k_sel, cudaFuncAttributeMaxDynamicSharedMemorySize, KSEL_SMEM);
    k_sel<<<dim3(5, NB), 1024, KSEL_SMEM>>>(p);
    cudaFuncSetAttribute(k_nms, cudaFuncAttributeMaxDynamicSharedMemorySize, K2_SMEM);
    k_nms<<<NB, 1024, K2_SMEM>>>((float*)d_out);
}

// round 10
// speedup vs baseline: 34.2759x; 1.4374x over previous
#include <cuda_runtime.h>
#include <math.h>

// Problem constants
#define NB 4          // batch
#define KTOT 4720     // concat candidates per image (1000*4 + 720)
#define IMGSZ 320.0f
#define THR 0.025f
#define IOUTHR 0.5f
#define NCLS 80

typedef unsigned long long u64;
typedef unsigned int u32;
typedef unsigned short u16;
typedef unsigned char u8;

// Per-level tables
__device__ __constant__ int   c_w[5]      = {40, 20, 10, 5, 3};
__device__ __constant__ int   c_A[5]      = {1600, 400, 100, 25, 9};
__device__ __constant__ int   c_stride[5] = {8, 16, 32, 64, 128};
__device__ __constant__ int   c_outoff[5] = {0, 1000, 2000, 3000, 4000};
__device__ __constant__ int   c_k[5]      = {1000, 1000, 1000, 1000, 720};

#define HBITS 13
#define HBINS (1 << HBITS)
#define HSHIFT (32 - HBITS)
#define BUF_CAP 8192

// Scratch (static device globals)
__device__ u64           g_skey[NB * KTOT];   // per-level segments sorted by final-score key
__device__ float4        g_box[NB * KTOT];    // indexed by concat position r (pre-sort)
__device__ u8            g_lab[NB * KTOT];
__device__ u8            g_valid[NB * KTOT];
__device__ float4        g_obox[NB * KTOT];   // offset boxes, sorted-row order
__device__ u8            g_slab[NB * KTOT];   // label | (valid<<7), sorted-row order

struct Ptrs {
    const float* cls[5];
    const float* bb[5];
    const float* ct[5];
};

__device__ __forceinline__ u32 ordf(float f) {
    u32 u = __float_as_uint(f);
    return (u & 0x80000000u) ? ~u : (u | 0x80000000u);
}
__device__ __forceinline__ float unordf(u32 u) {
    return __uint_as_float((u & 0x80000000u) ? (u & 0x7FFFFFFFu) : ~u);
}

// XLA:CPU f32 exp (Eigen/Cephes pexp) with FMA contraction. PROTECT: bit-exact.
__device__ __forceinline__ float xla_cpu_expf(float x) {
    x = fminf(x,  88.3762626647950f);
    x = fmaxf(x, -88.3762626647949f);
    float fx = floorf(__fmaf_rn(x, 1.44269504088896341f, 0.5f));
    float r = __fmaf_rn(fx, -0.693359375f, x);
    r = __fmaf_rn(fx, 2.12194440e-4f, r);
    float r2 = __fmul_rn(r, r);
    float y = 1.9875691500e-4f;
    y = __fmaf_rn(y, r, 1.3981999507e-3f);
    y = __fmaf_rn(y, r, 8.3334519073e-3f);
    y = __fmaf_rn(y, r, 4.1665795894e-2f);
    y = __fmaf_rn(y, r, 1.6666665459e-1f);
    y = __fmaf_rn(y, r, 5.0000001201e-1f);
    y = __fmaf_rn(y, r2, r);
    y = __fadd_rn(y, 1.0f);
    int n = (int)fx;
    float s = __int_as_float((u32)(n + 127) << 23);
    return __fmul_rn(y, s);
}
__device__ __forceinline__ float sigm(float x) {
    return __fdiv_rn(1.0f, __fadd_rn(1.0f, xla_cpu_expf(-x)));
}

// IoU on offset boxes, exact reference float op order. PROTECT.
__device__ __forceinline__ bool suppresses(const float4 a, const float4 b) {
    float aa = __fmul_rn(__fsub_rn(a.z, a.x), __fsub_rn(a.w, a.y));
    float ab = __fmul_rn(__fsub_rn(b.z, b.x), __fsub_rn(b.w, b.y));
    float ltx = fmaxf(a.x, b.x), lty = fmaxf(a.y, b.y);
    float rbx = fminf(a.z, b.z), rby = fminf(a.w, b.w);
    float w = fmaxf(__fsub_rn(rbx, ltx), 0.0f), h = fmaxf(__fsub_rn(rby, lty), 0.0f);
    float inter = __fmul_rn(w, h);
    float uni = __fsub_rn(__fadd_rn(aa, ab), inter);
    float iou = (uni > 0.0f) ? __fdiv_rn(inter, uni) : 0.0f;
    return iou > IOUTHR;
}

// Generic bitonic sort of buf[0..P) in SMEM, P power of 2, all 1024 threads.
__device__ __forceinline__ void bitonic_smem(u64* buf, int P, int tid) {
    for (int ks2 = 2; ks2 <= P; ks2 <<= 1) {
        for (int j = ks2 >> 1; j > 0; j >>= 1) {
            for (int e = tid; e < P; e += 1024) {
                int ixj = e ^ j;
                if (ixj > e) {
                    u64 a = buf[e], bv = buf[ixj];
                    if ((a > bv) == ((e & ks2) == 0)) { buf[e] = bv; buf[ixj] = a; }
                }
            }
            __syncthreads();
        }
    }
}

// Merge-path pick: output element i of merge(A[0..n), B[0..m)); keys unique.
__device__ __forceinline__ u64 merge_pick(const u64* A, int n, const u64* Bb, int m, int i) {
    int lo = max(0, i - m), hi = min(i, n);
    while (lo < hi) {
        int mid = (lo + hi) >> 1;
        if (A[mid] < Bb[i - 1 - mid]) lo = mid + 1; else hi = mid;
    }
    int a = lo, bj = i - lo;
    if (a >= n) return Bb[bj];
    if (bj >= m) return A[a];
    u64 va = A[a], vb = Bb[bj];
    return va < vb ? va : vb;
}

// ---------------------------------------------------------------------------
// Kernel 1: per (lvl,b) block — fused histogram + select (unchanged).
// ---------------------------------------------------------------------------
#define SEL_H_OFF 0
#define SEL_B_OFF 32768
#define SEL_F_OFF (32768 + 65536)
#define KSEL_SMEM (SEL_F_OFF + 8192)

__global__ __launch_bounds__(1024) void k_sel(Ptrs p) {
    const int lvl = blockIdx.x;
    const int b = blockIdx.y;
    const int tid = threadIdx.x;
    const int lane = tid & 31, wid = tid >> 5;

    const int w = c_w[lvl];
    const int A = c_A[lvl];
    const int N = A * 80;
    const int k = c_k[lvl];
    const int stride = c_stride[lvl];

    const float* cls = p.cls[lvl] + (size_t)b * N;

    extern __shared__ unsigned char smraw[];
    u32* hist = (u32*)(smraw + SEL_H_OFF);
    u64* buf = (u64*)(smraw + SEL_B_OFF);
    u64* fin = (u64*)(smraw + SEL_F_OFF);

    __shared__ u32 s_wsum[32];
    __shared__ int s_B;
    __shared__ u32 s_cnt;

    #pragma unroll
    for (int i = tid; i < HBINS; i += 1024) hist[i] = 0;
    __syncthreads();

    const float4* cls4 = (const float4*)cls;
    const int N4 = N >> 2;
    for (int i = tid; i < N4; i += 1024) {
        float4 v = cls4[i];
        atomicAdd(&hist[(~ordf(v.x)) >> HSHIFT], 1u);
        atomicAdd(&hist[(~ordf(v.y)) >> HSHIFT], 1u);
        atomicAdd(&hist[(~ordf(v.z)) >> HSHIFT], 1u);
        atomicAdd(&hist[(~ordf(v.w)) >> HSHIFT], 1u);
    }
    __syncthreads();

    const int b0 = tid * (HBINS / 1024);
    u32 bins[HBINS / 1024];
    u32 st = 0;
    #pragma unroll
    for (int j = 0; j < HBINS / 1024; j++) { bins[j] = hist[b0 + j]; st += bins[j]; }
    u32 incl = st;
    #pragma unroll
    for (int o = 1; o < 32; o <<= 1) {
        u32 v = __shfl_up_sync(0xFFFFFFFFu, incl, o);
        if (lane >= o) incl += v;
    }
    if (lane == 31) s_wsum[wid] = incl;
    __syncthreads();
    if (wid == 0) {
        u32 v = s_wsum[lane];
        #pragma unroll
        for (int o = 1; o < 32; o <<= 1) {
            u32 t2 = __shfl_up_sync(0xFFFFFFFFu, v, o);
            if (lane >= o) v += t2;
        }
        s_wsum[lane] = v;
    }
    __syncthreads();
    u32 myexcl = (wid ? s_wsum[wid - 1] : 0u) + (incl - st);
    if (myexcl < (u32)k && myexcl + st >= (u32)k) {
        u32 cum = myexcl;
        #pragma unroll
        for (int j = 0; j < HBINS / 1024; j++) {
            if (cum + bins[j] >= (u32)k) { s_B = b0 + j; break; }
            cum += bins[j];
        }
    }
    if (tid == 0) s_cnt = 0;
    __syncthreads();
    const u32 Bg = (u32)s_B + 1;   // guard bin included

    for (int i = tid; i < N; i += 1024) {
        float x = cls[i];
        u32 pl = (~ordf(x)) >> HSHIFT;
        if (pl <= Bg) {
            float s = sigm(x);
            float mv = (s > THR) ? s : -1.0f;
            int c = i / A;
            int anchor = i - c * A;
            u64 key = ((u64)(~ordf(mv)) << 32) | (u32)(anchor * 80 + c);
            u32 pos = atomicAdd(&s_cnt, 1u);
            if (pos < BUF_CAP) buf[pos] = key;
        }
    }
    __syncthreads();
    int nG = (int)min(s_cnt, (u32)BUF_CAP);

    int P = 2;
    while (P < nG) P <<= 1;
    if (P < 1024) P = 1024;
    for (int e = tid; e < P; e += 1024) if (e >= nG) buf[e] = ~0ull;
    __syncthreads();
    bitonic_smem(buf, P, tid);

    u64 fkey = ~0ull;
    if (tid < k) {
        u64 key = buf[tid];
        int e = (int)(key & 0xFFFFFFFFull);
        float mv = unordf(~(u32)(key >> 32));
        int anchor = e / 80;
        int lab = e - anchor * 80;
        int y = anchor / w;
        int x = anchor - y * w;
        const float* bb = p.bb[lvl];
        const float* ct = p.ct[lvl];
        float sf = sigm(ct[(size_t)b * A + anchor]);
        float dl = bb[((size_t)b * 4 + 0) * A + anchor];
        float dt = bb[((size_t)b * 4 + 1) * A + anchor];
        float dr = bb[((size_t)b * 4 + 2) * A + anchor];
        float db = bb[((size_t)b * 4 + 3) * A + anchor];
        float px = __fmul_rn(__fadd_rn((float)x, 0.5f), (float)stride);
        float py = __fmul_rn(__fadd_rn((float)y, 0.5f), (float)stride);
        float4 bx;
        bx.x = fminf(fmaxf(__fsub_rn(px, dl), 0.0f), IMGSZ);
        bx.y = fminf(fmaxf(__fsub_rn(py, dt), 0.0f), IMGSZ);
        bx.z = fminf(fmaxf(__fadd_rn(px, dr), 0.0f), IMGSZ);
        bx.w = fminf(fmaxf(__fadd_rn(py, db), 0.0f), IMGSZ);
        bool valid = mv > THR;
        float score = valid ? __fmul_rn(mv, sf) : -1.0f;
        int r = c_outoff[lvl] + tid;    // reference concat position
        int g = b * KTOT + r;
        g_box[g] = bx;
        g_lab[g] = (u8)lab;
        g_valid[g] = valid ? 1 : 0;
        fkey = ((u64)(~ordf(score)) << 32) | (u32)r;
    }
    fin[tid] = fkey;
    __syncthreads();

    bitonic_smem(fin, 1024, tid);
    if (tid < k) g_skey[b * KTOT + c_outoff[lvl] + tid] = fin[tid];
}

// ---------------------------------------------------------------------------
// Kernel 2: per image — max-coord, 3-round merge-path merge of 5 sorted
// segments (keys unique => identical permutation to full sort), write
// dets/labels, emit offset boxes + label|valid bytes in sorted-row order.
// smem: bufA u64[4720] + bufB u64[4720] = 75520 B.
// ---------------------------------------------------------------------------
#define KSORT_SMEM (KTOT * 8 * 2)

__global__ __launch_bounds__(1024) void k_sort(float* __restrict__ out) {
    const int b = blockIdx.x;
    const int tid = threadIdx.x;
    const int K = KTOT;
    const int lane = tid & 31, wid = tid >> 5;

    extern __shared__ unsigned char smraw[];
    u64* bufA = (u64*)smraw;
    u64* bufB = (u64*)(smraw + KTOT * 8);

    __shared__ float s_red[32];
    __shared__ float s_maxc;

    // max over all box coords of this image
    const float* bf = (const float*)(g_box + b * K);
    float m = -3.0e38f;
    for (int e = tid; e < K * 4; e += 1024) m = fmaxf(m, bf[e]);
    #pragma unroll
    for (int o = 16; o; o >>= 1) m = fmaxf(m, __shfl_xor_sync(0xFFFFFFFFu, m, o));
    if (lane == 0) s_red[wid] = m;
    __syncthreads();
    if (tid == 0) {
        float v = s_red[0];
        for (int i = 1; i < 32; i++) v = fmaxf(v, s_red[i]);
        s_maxc = v;
    }

    // load per-level sorted segments
    for (int e = tid; e < K; e += 1024) bufA[e] = g_skey[b * K + e];
    __syncthreads();
    float maxc1 = __fadd_rn(s_maxc, 1.0f);

    // round 1: (L0,L1)->B[0,2000), (L2,L3)->B[2000,4000), copy L4
    #pragma unroll
    for (int mr = 0; mr < 5; mr++) {
        int e = tid + mr * 1024;
        if (e < K) {
            u64 v;
            if (e < 2000)      v = merge_pick(bufA,        1000, bufA + 1000, 1000, e);
            else if (e < 4000) v = merge_pick(bufA + 2000, 1000, bufA + 3000, 1000, e - 2000);
            else               v = bufA[e];
            bufB[e] = v;
        }
    }
    __syncthreads();

    // round 2: (M01,M23)->A[0,4000), copy tail
    #pragma unroll
    for (int mr = 0; mr < 5; mr++) {
        int e = tid + mr * 1024;
        if (e < K) {
            u64 v;
            if (e < 4000) v = merge_pick(bufB, 2000, bufB + 2000, 2000, e);
            else          v = bufB[e];
            bufA[e] = v;
        }
    }
    __syncthreads();

    // round 3: (M0123, L4) -> B[0,4720)
    #pragma unroll
    for (int mr = 0; mr < 5; mr++) {
        int e = tid + mr * 1024;
        if (e < K) bufB[e] = merge_pick(bufA, 4000, bufA + 4000, 720, e);
    }
    __syncthreads();

    float* outD = out + (size_t)b * K * 5;
    float* outL = out + (size_t)NB * K * 5 + (size_t)b * K;

    #pragma unroll
    for (int mr = 0; mr < 5; mr++) {
        int r = tid + mr * 1024;
        if (r < K) {
            u64 key = bufB[r];
            int src = (int)(key & 0xFFFFFFFFull);
            float sc = unordf(~(u32)(key >> 32));
            float4 bx = g_box[b * K + src];
            int lab = g_lab[b * K + src];
            u8 valid = g_valid[b * K + src];
            outD[r * 5 + 0] = bx.x;
            outD[r * 5 + 1] = bx.y;
            outD[r * 5 + 2] = bx.z;
            outD[r * 5 + 3] = bx.w;
            outD[r * 5 + 4] = sc;
            outL[r] = (float)lab;
            float off = __fmul_rn((float)lab, maxc1);
            float4 ob;
            ob.x = __fadd_rn(bx.x, off); ob.y = __fadd_rn(bx.y, off);
            ob.z = __fadd_rn(bx.z, off); ob.w = __fadd_rn(bx.w, off);
            g_obox[b * K + r] = ob;
            g_slab[b * K + r] = (u8)(lab | (valid << 7));
        }
    }
}

// ---------------------------------------------------------------------------
// Kernel 3: one warp per (class, image) — ballot-compact class rows in sorted
// order, greedy NMS (exact: cross-class IoU == 0, class order == global order
// restricted to class), write keep for exactly this class's rows.
// ---------------------------------------------------------------------------
#define KNMS2_SMEM (KTOT * 2 + KTOT + KTOT * 16 + 16)

__global__ __launch_bounds__(32) void k_nms2(float* __restrict__ out) {
    const int c = blockIdx.x;
    const int b = blockIdx.y;
    const int lane = threadIdx.x;
    const int K = KTOT;

    extern __shared__ unsigned char smraw[];
    u16* s_idx = (u16*)smraw;                          // [K]
    u8* s_alive = smraw + K * 2;                       // [K]
    float4* s_box = (float4*)(smraw + ((K * 3 + 15) & ~15)); // [K]

    const u8* slab = g_slab + b * K;

    // ballot compaction in sorted-row order
    int cnt = 0;
    for (int it = 0; it < (K + 31) / 32; it++) {
        int r = it * 32 + lane;
        u8 byte = (r < K) ? slab[r] : 0xFF;
        bool match = (r < K) && ((byte & 0x7F) == c);
        u32 mask = __ballot_sync(0xFFFFFFFFu, match);
        if (match) {
            int pos = cnt + __popc(mask & ((1u << lane) - 1u));
            s_idx[pos] = (u16)r;
            s_alive[pos] = byte >> 7;
        }
        cnt += __popc(mask);
    }
    __syncwarp();

    // load offset boxes for this class
    for (int i = lane; i < cnt; i += 32) s_box[i] = g_obox[b * K + s_idx[i]];
    __syncwarp();

    // greedy (sequential in sorted order, lane-parallel suppression)
    for (int i = 0; i < cnt; i++) {
        if (s_alive[i]) {
            float4 bi = s_box[i];
            for (int j = i + 1 + lane; j < cnt; j += 32) {
                if (s_alive[j] && suppresses(bi, s_box[j])) s_alive[j] = 0;
            }
        }
        __syncwarp();
    }

    float* outKp = out + (size_t)NB * K * 5 + (size_t)NB * K + (size_t)b * K;
    for (int i = lane; i < cnt; i += 32)
        outKp[s_idx[i]] = s_alive[i] ? 1.0f : 0.0f;
}

// ---------------------------------------------------------------------------
extern "C" void kernel_launch(void* const* d_in, const int* in_sizes, int n_in,
                              void* d_out, int out_size) {
    (void)n_in; (void)out_size;
    Ptrs p;
    bool interleaved = (in_sizes[1] == 25600);
    for (int i = 0; i < 5; i++) {
        if (interleaved) {
            p.cls[i] = (const float*)d_in[3 * i + 0];
            p.bb[i]  = (const float*)d_in[3 * i + 1];
            p.ct[i]  = (const float*)d_in[3 * i + 2];
        } else {
            p.cls[i] = (const float*)d_in[i];
            p.bb[i]  = (const float*)d_in[5 + i];
            p.ct[i]  = (const float*)d_in[10 + i];
        }
    }
    cudaFuncSetAttribute(k_sel, cudaFuncAttributeMaxDynamicSharedMemorySize, KSEL_SMEM);
    k_sel<<<dim3(5, NB), 1024, KSEL_SMEM>>>(p);
    cudaFuncSetAttribute(k_sort, cudaFuncAttributeMaxDynamicSharedMemorySize, KSORT_SMEM);
    k_sort<<<NB, 1024, KSORT_SMEM>>>((float*)d_out);
    cudaFuncSetAttribute(k_nms2, cudaFuncAttributeMaxDynamicSharedMemorySize, KNMS2_SMEM);
    k_nms2<<<dim3(NCLS, NB), 32, KNMS2_SMEM>>>((float*)d_out);
}

// round 11
// speedup vs baseline: 37.9954x; 1.1085x over previous
#include <cuda_runtime.h>
#include <math.h>

// Problem constants
#define NB 4          // batch
#define KTOT 4720     // concat candidates per image (1000*4 + 720)
#define IMGSZ 320.0f
#define THR 0.025f
#define IOUTHR 0.5f
#define NCLS 80

typedef unsigned long long u64;
typedef unsigned int u32;
typedef unsigned short u16;
typedef unsigned char u8;

// Per-level tables
__device__ __constant__ int   c_w[5]      = {40, 20, 10, 5, 3};
__device__ __constant__ int   c_A[5]      = {1600, 400, 100, 25, 9};
__device__ __constant__ int   c_stride[5] = {8, 16, 32, 64, 128};
__device__ __constant__ int   c_outoff[5] = {0, 1000, 2000, 3000, 4000};
__device__ __constant__ int   c_k[5]      = {1000, 1000, 1000, 1000, 720};

#define HBITS 13
#define HBINS (1 << HBITS)
#define HSHIFT (32 - HBITS)
#define BUF_CAP 8192

// Scratch (static device globals)
__device__ u64           g_skey[NB * KTOT];   // per-level segments sorted by final-score key
__device__ float4        g_box[NB * KTOT];    // indexed by concat position r (pre-sort)
__device__ u8            g_lab[NB * KTOT];
__device__ u8            g_valid[NB * KTOT];
__device__ float4        g_obox[NB * KTOT];   // offset boxes, sorted-row order
__device__ u8            g_slab[NB * KTOT];   // label | (valid<<7), sorted-row order

struct Ptrs {
    const float* cls[5];
    const float* bb[5];
    const float* ct[5];
};

__device__ __forceinline__ u32 ordf(float f) {
    u32 u = __float_as_uint(f);
    return (u & 0x80000000u) ? ~u : (u | 0x80000000u);
}
__device__ __forceinline__ float unordf(u32 u) {
    return __uint_as_float((u & 0x80000000u) ? (u & 0x7FFFFFFFu) : ~u);
}

// XLA:CPU f32 exp (Eigen/Cephes pexp) with FMA contraction. PROTECT: bit-exact.
__device__ __forceinline__ float xla_cpu_expf(float x) {
    x = fminf(x,  88.3762626647950f);
    x = fmaxf(x, -88.3762626647949f);
    float fx = floorf(__fmaf_rn(x, 1.44269504088896341f, 0.5f));
    float r = __fmaf_rn(fx, -0.693359375f, x);
    r = __fmaf_rn(fx, 2.12194440e-4f, r);
    float r2 = __fmul_rn(r, r);
    float y = 1.9875691500e-4f;
    y = __fmaf_rn(y, r, 1.3981999507e-3f);
    y = __fmaf_rn(y, r, 8.3334519073e-3f);
    y = __fmaf_rn(y, r, 4.1665795894e-2f);
    y = __fmaf_rn(y, r, 1.6666665459e-1f);
    y = __fmaf_rn(y, r, 5.0000001201e-1f);
    y = __fmaf_rn(y, r2, r);
    y = __fadd_rn(y, 1.0f);
    int n = (int)fx;
    float s = __int_as_float((u32)(n + 127) << 23);
    return __fmul_rn(y, s);
}
__device__ __forceinline__ float sigm(float x) {
    return __fdiv_rn(1.0f, __fadd_rn(1.0f, xla_cpu_expf(-x)));
}

// IoU on offset boxes, exact reference float op order. PROTECT.
__device__ __forceinline__ bool suppresses(const float4 a, const float4 b) {
    float aa = __fmul_rn(__fsub_rn(a.z, a.x), __fsub_rn(a.w, a.y));
    float ab = __fmul_rn(__fsub_rn(b.z, b.x), __fsub_rn(b.w, b.y));
    float ltx = fmaxf(a.x, b.x), lty = fmaxf(a.y, b.y);
    float rbx = fminf(a.z, b.z), rby = fminf(a.w, b.w);
    float w = fmaxf(__fsub_rn(rbx, ltx), 0.0f), h = fmaxf(__fsub_rn(rby, lty), 0.0f);
    float inter = __fmul_rn(w, h);
    float uni = __fsub_rn(__fadd_rn(aa, ab), inter);
    float iou = (uni > 0.0f) ? __fdiv_rn(inter, uni) : 0.0f;
    return iou > IOUTHR;
}

// Merge-path pick: output element i of merge(A[0..n), B[0..m)); keys unique.
__device__ __forceinline__ u64 merge_pick(const u64* A, int n, const u64* Bb, int m, int i) {
    int lo = max(0, i - m), hi = min(i, n);
    while (lo < hi) {
        int mid = (lo + hi) >> 1;
        if (A[mid] < Bb[i - 1 - mid]) lo = mid + 1; else hi = mid;
    }
    int a = lo, bj = i - lo;
    if (a >= n) return Bb[bj];
    if (bj >= m) return A[a];
    u64 va = A[a], vb = Bb[bj];
    return va < vb ? va : vb;
}

// Warp-register bitonic sort of 32 u64 (ascending across lanes), no barriers.
__device__ __forceinline__ u64 warp_sort32(u64 v, int lane) {
    #pragma unroll
    for (int k2 = 2; k2 <= 32; k2 <<= 1) {
        #pragma unroll
        for (int j = k2 >> 1; j > 0; j >>= 1) {
            u64 o = __shfl_xor_sync(0xFFFFFFFFu, v, j);
            bool up = ((lane & k2) == 0);
            bool lower = ((lane & j) == 0);
            v = ((lower == up) ? (v < o ? v : o) : (v > o ? v : o));
        }
    }
    return v;
}

// Sort src[0..P) ascending (P power of 2 >= 1024, multiple of 32), using aux
// as ping-pong. Warp-sorted 32-runs + merge-path rounds (1 barrier per round).
// Returns pointer holding the sorted data (src or aux).
__device__ u64* msort(u64* src, u64* aux, int P, int tid) {
    const int lane = tid & 31, wid = tid >> 5;
    for (int r = wid; r < (P >> 5); r += 32) {
        u64 v = src[r * 32 + lane];
        src[r * 32 + lane] = warp_sort32(v, lane);
    }
    __syncthreads();
    u64 *s = src, *d = aux;
    for (int L = 32; L < P; L <<= 1) {
        for (int e = tid; e < P; e += 1024) {
            int seg = (e / (L << 1)) * (L << 1);
            d[e] = merge_pick(s + seg, L, s + seg + L, L, e - seg);
        }
        __syncthreads();
        u64* t = s; s = d; d = t;
    }
    return s;
}

// ---------------------------------------------------------------------------
// Kernel 1: per (lvl,b) block — fused histogram + select.
// smem: hist u32[8192] | buf u64[8192] | aux u64[8192] | fin u64[1024]
// ---------------------------------------------------------------------------
#define SEL_H_OFF 0
#define SEL_B_OFF 32768
#define SEL_X_OFF (32768 + 65536)
#define SEL_F_OFF (32768 + 65536 + 65536)
#define KSEL_SMEM (SEL_F_OFF + 8192)

__global__ __launch_bounds__(1024) void k_sel(Ptrs p) {
    const int lvl = blockIdx.x;
    const int b = blockIdx.y;
    const int tid = threadIdx.x;
    const int lane = tid & 31, wid = tid >> 5;

    const int w = c_w[lvl];
    const int A = c_A[lvl];
    const int N = A * 80;
    const int k = c_k[lvl];
    const int stride = c_stride[lvl];

    const float* cls = p.cls[lvl] + (size_t)b * N;

    extern __shared__ unsigned char smraw[];
    u32* hist = (u32*)(smraw + SEL_H_OFF);
    u64* buf = (u64*)(smraw + SEL_B_OFF);
    u64* aux = (u64*)(smraw + SEL_X_OFF);
    u64* fin = (u64*)(smraw + SEL_F_OFF);

    __shared__ u32 s_wsum[32];
    __shared__ int s_B;
    __shared__ u32 s_cnt;

    #pragma unroll
    for (int i = tid; i < HBINS; i += 1024) hist[i] = 0;
    __syncthreads();

    // pass1: logit-ordinal histogram (no sigmoid), float4 loads
    const float4* cls4 = (const float4*)cls;
    const int N4 = N >> 2;
    for (int i = tid; i < N4; i += 1024) {
        float4 v = cls4[i];
        atomicAdd(&hist[(~ordf(v.x)) >> HSHIFT], 1u);
        atomicAdd(&hist[(~ordf(v.y)) >> HSHIFT], 1u);
        atomicAdd(&hist[(~ordf(v.z)) >> HSHIFT], 1u);
        atomicAdd(&hist[(~ordf(v.w)) >> HSHIFT], 1u);
    }
    __syncthreads();

    // scan bins, find k-th crossing
    const int b0 = tid * (HBINS / 1024);
    u32 bins[HBINS / 1024];
    u32 st = 0;
    #pragma unroll
    for (int j = 0; j < HBINS / 1024; j++) { bins[j] = hist[b0 + j]; st += bins[j]; }
    u32 incl = st;
    #pragma unroll
    for (int o = 1; o < 32; o <<= 1) {
        u32 v = __shfl_up_sync(0xFFFFFFFFu, incl, o);
        if (lane >= o) incl += v;
    }
    if (lane == 31) s_wsum[wid] = incl;
    __syncthreads();
    if (wid == 0) {
        u32 v = s_wsum[lane];
        #pragma unroll
        for (int o = 1; o < 32; o <<= 1) {
            u32 t2 = __shfl_up_sync(0xFFFFFFFFu, v, o);
            if (lane >= o) v += t2;
        }
        s_wsum[lane] = v;
    }
    __syncthreads();
    u32 myexcl = (wid ? s_wsum[wid - 1] : 0u) + (incl - st);
    if (myexcl < (u32)k && myexcl + st >= (u32)k) {
        u32 cum = myexcl;
        #pragma unroll
        for (int j = 0; j < HBINS / 1024; j++) {
            if (cum + bins[j] >= (u32)k) { s_B = b0 + j; break; }
            cum += bins[j];
        }
    }
    if (tid == 0) s_cnt = 0;
    __syncthreads();
    const u32 Bg = (u32)s_B + 1;   // guard bin included (covers all score ties)

    // pass2: gather (cheap logit-prefix cull; exact score key for survivors)
    for (int i = tid; i < N; i += 1024) {
        float x = cls[i];
        u32 pl = (~ordf(x)) >> HSHIFT;
        if (pl <= Bg) {
            float s = sigm(x);
            float mv = (s > THR) ? s : -1.0f;
            int c = i / A;
            int anchor = i - c * A;
            u64 key = ((u64)(~ordf(mv)) << 32) | (u32)(anchor * 80 + c);
            u32 pos = atomicAdd(&s_cnt, 1u);
            if (pos < BUF_CAP) buf[pos] = key;
        }
    }
    __syncthreads();
    int nG = (int)min(s_cnt, (u32)BUF_CAP);

    int P = 1024;
    while (P < nG) P <<= 1;
    for (int e = tid; e < P; e += 1024) if (e >= nG) buf[e] = ~0ull;
    __syncthreads();
    u64* res = msort(buf, aux, P, tid);

    // decode + emit top-k (exact float ops — PROTECT); build final-score keys
    u64 fkey = ~0ull;
    if (tid < k) {
        u64 key = res[tid];
        int e = (int)(key & 0xFFFFFFFFull);
        float mv = unordf(~(u32)(key >> 32));
        int anchor = e / 80;
        int lab = e - anchor * 80;
        int y = anchor / w;
        int x = anchor - y * w;
        const float* bb = p.bb[lvl];
        const float* ct = p.ct[lvl];
        float sf = sigm(ct[(size_t)b * A + anchor]);
        float dl = bb[((size_t)b * 4 + 0) * A + anchor];
        float dt = bb[((size_t)b * 4 + 1) * A + anchor];
        float dr = bb[((size_t)b * 4 + 2) * A + anchor];
        float db = bb[((size_t)b * 4 + 3) * A + anchor];
        float px = __fmul_rn(__fadd_rn((float)x, 0.5f), (float)stride);
        float py = __fmul_rn(__fadd_rn((float)y, 0.5f), (float)stride);
        float4 bx;
        bx.x = fminf(fmaxf(__fsub_rn(px, dl), 0.0f), IMGSZ);
        bx.y = fminf(fmaxf(__fsub_rn(py, dt), 0.0f), IMGSZ);
        bx.z = fminf(fmaxf(__fadd_rn(px, dr), 0.0f), IMGSZ);
        bx.w = fminf(fmaxf(__fadd_rn(py, db), 0.0f), IMGSZ);
        bool valid = mv > THR;
        float score = valid ? __fmul_rn(mv, sf) : -1.0f;
        int r = c_outoff[lvl] + tid;    // reference concat position
        int g = b * KTOT + r;
        g_box[g] = bx;
        g_lab[g] = (u8)lab;
        g_valid[g] = valid ? 1 : 0;
        fkey = ((u64)(~ordf(score)) << 32) | (u32)r;
    }
    fin[tid] = fkey;
    __syncthreads();

    // per-level sort by final-score key (unique keys)
    u64* res2 = msort(fin, aux, 1024, tid);
    if (tid < k) g_skey[b * KTOT + c_outoff[lvl] + tid] = res2[tid];
}

// ---------------------------------------------------------------------------
// Kernel 2: per image — max-coord, 3-round merge-path merge of 5 sorted
// segments (keys unique => identical permutation to full sort), write
// dets/labels, emit offset boxes + label|valid bytes in sorted-row order.
// ---------------------------------------------------------------------------
#define KSORT_SMEM (KTOT * 8 * 2)

__global__ __launch_bounds__(1024) void k_sort(float* __restrict__ out) {
    const int b = blockIdx.x;
    const int tid = threadIdx.x;
    const int K = KTOT;
    const int lane = tid & 31, wid = tid >> 5;

    extern __shared__ unsigned char smraw[];
    u64* bufA = (u64*)smraw;
    u64* bufB = (u64*)(smraw + KTOT * 8);

    __shared__ float s_red[32];
    __shared__ float s_maxc;

    const float* bf = (const float*)(g_box + b * K);
    float m = -3.0e38f;
    for (int e = tid; e < K * 4; e += 1024) m = fmaxf(m, bf[e]);
    #pragma unroll
    for (int o = 16; o; o >>= 1) m = fmaxf(m, __shfl_xor_sync(0xFFFFFFFFu, m, o));
    if (lane == 0) s_red[wid] = m;
    __syncthreads();
    if (tid == 0) {
        float v = s_red[0];
        for (int i = 1; i < 32; i++) v = fmaxf(v, s_red[i]);
        s_maxc = v;
    }

    for (int e = tid; e < K; e += 1024) bufA[e] = g_skey[b * K + e];
    __syncthreads();
    float maxc1 = __fadd_rn(s_maxc, 1.0f);

    #pragma unroll
    for (int mr = 0; mr < 5; mr++) {
        int e = tid + mr * 1024;
        if (e < K) {
            u64 v;
            if (e < 2000)      v = merge_pick(bufA,        1000, bufA + 1000, 1000, e);
            else if (e < 4000) v = merge_pick(bufA + 2000, 1000, bufA + 3000, 1000, e - 2000);
            else               v = bufA[e];
            bufB[e] = v;
        }
    }
    __syncthreads();

    #pragma unroll
    for (int mr = 0; mr < 5; mr++) {
        int e = tid + mr * 1024;
        if (e < K) {
            u64 v;
            if (e < 4000) v = merge_pick(bufB, 2000, bufB + 2000, 2000, e);
            else          v = bufB[e];
            bufA[e] = v;
        }
    }
    __syncthreads();

    #pragma unroll
    for (int mr = 0; mr < 5; mr++) {
        int e = tid + mr * 1024;
        if (e < K) bufB[e] = merge_pick(bufA, 4000, bufA + 4000, 720, e);
    }
    __syncthreads();

    float* outD = out + (size_t)b * K * 5;
    float* outL = out + (size_t)NB * K * 5 + (size_t)b * K;

    #pragma unroll
    for (int mr = 0; mr < 5; mr++) {
        int r = tid + mr * 1024;
        if (r < K) {
            u64 key = bufB[r];
            int src = (int)(key & 0xFFFFFFFFull);
            float sc = unordf(~(u32)(key >> 32));
            float4 bx = g_box[b * K + src];
            int lab = g_lab[b * K + src];
            u8 valid = g_valid[b * K + src];
            outD[r * 5 + 0] = bx.x;
            outD[r * 5 + 1] = bx.y;
            outD[r * 5 + 2] = bx.z;
            outD[r * 5 + 3] = bx.w;
            outD[r * 5 + 4] = sc;
            outL[r] = (float)lab;
            float off = __fmul_rn((float)lab, maxc1);
            float4 ob;
            ob.x = __fadd_rn(bx.x, off); ob.y = __fadd_rn(bx.y, off);
            ob.z = __fadd_rn(bx.z, off); ob.w = __fadd_rn(bx.w, off);
            g_obox[b * K + r] = ob;
            g_slab[b * K + r] = (u8)(lab | (valid << 7));
        }
    }
}

// ---------------------------------------------------------------------------
// Kernel 3: one warp per (class, image) — ballot-compact class rows in sorted
// order, greedy NMS (exact: cross-class IoU == 0), write keep for class rows.
// ---------------------------------------------------------------------------
#define KNMS2_SMEM (KTOT * 2 + KTOT + KTOT * 16 + 16)

__global__ __launch_bounds__(32) void k_nms2(float* __restrict__ out) {
    const int c = blockIdx.x;
    const int b = blockIdx.y;
    const int lane = threadIdx.x;
    const int K = KTOT;

    extern __shared__ unsigned char smraw[];
    u16* s_idx = (u16*)smraw;
    u8* s_alive = smraw + K * 2;
    float4* s_box = (float4*)(smraw + ((K * 3 + 15) & ~15));

    const u8* slab = g_slab + b * K;

    int cnt = 0;
    for (int it = 0; it < (K + 31) / 32; it++) {
        int r = it * 32 + lane;
        u8 byte = (r < K) ? slab[r] : 0xFF;
        bool match = (r < K) && ((byte & 0x7F) == c);
        u32 mask = __ballot_sync(0xFFFFFFFFu, match);
        if (match) {
            int pos = cnt + __popc(mask & ((1u << lane) - 1u));
            s_idx[pos] = (u16)r;
            s_alive[pos] = byte >> 7;
        }
        cnt += __popc(mask);
    }
    __syncwarp();

    for (int i = lane; i < cnt; i += 32) s_box[i] = g_obox[b * K + s_idx[i]];
    __syncwarp();

    for (int i = 0; i < cnt; i++) {
        if (s_alive[i]) {
            float4 bi = s_box[i];
            for (int j = i + 1 + lane; j < cnt; j += 32) {
                if (s_alive[j] && suppresses(bi, s_box[j])) s_alive[j] = 0;
            }
        }
        __syncwarp();
    }

    float* outKp = out + (size_t)NB * K * 5 + (size_t)NB * K + (size_t)b * K;
    for (int i = lane; i < cnt; i += 32)
        outKp[s_idx[i]] = s_alive[i] ? 1.0f : 0.0f;
}

// ---------------------------------------------------------------------------
extern "C" void kernel_launch(void* const* d_in, const int* in_sizes, int n_in,
                              void* d_out, int out_size) {
    (void)n_in; (void)out_size;
    Ptrs p;
    bool interleaved = (in_sizes[1] == 25600);
    for (int i = 0; i < 5; i++) {
        if (interleaved) {
            p.cls[i] = (const float*)d_in[3 * i + 0];
            p.bb[i]  = (const float*)d_in[3 * i + 1];
            p.ct[i]  = (const float*)d_in[3 * i + 2];
        } else {
            p.cls[i] = (const float*)d_in[i];
            p.bb[i]  = (const float*)d_in[5 + i];
            p.ct[i]  = (const float*)d_in[10 + i];
        }
    }
    cudaFuncSetAttribute(k_sel, cudaFuncAttributeMaxDynamicSharedMemorySize, KSEL_SMEM);
    k_sel<<<dim3(5, NB), 1024, KSEL_SMEM>>>(p);
    cudaFuncSetAttribute(k_sort, cudaFuncAttributeMaxDynamicSharedMemorySize, KSORT_SMEM);
    k_sort<<<NB, 1024, KSORT_SMEM>>>((float*)d_out);
    cudaFuncSetAttribute(k_nms2, cudaFuncAttributeMaxDynamicSharedMemorySize, KNMS2_SMEM);
    k_nms2<<<dim3(NCLS, NB), 32, KNMS2_SMEM>>>((float*)d_out);
}

// round 12
// speedup vs baseline: 44.9294x; 1.1825x over previous
#include <cuda_runtime.h>
#include <math.h>

// Problem constants
#define NB 4          // batch
#define KTOT 4720     // concat candidates per image (1000*4 + 720)
#define IMGSZ 320.0f
#define THR 0.025f
#define IOUTHR 0.5f
#define NCLS 80

typedef unsigned long long u64;
typedef unsigned int u32;
typedef unsigned short u16;
typedef unsigned char u8;

// Per-level tables
__device__ __constant__ int   c_w[5]      = {40, 20, 10, 5, 3};
__device__ __constant__ int   c_A[5]      = {1600, 400, 100, 25, 9};
__device__ __constant__ int   c_stride[5] = {8, 16, 32, 64, 128};
__device__ __constant__ int   c_outoff[5] = {0, 1000, 2000, 3000, 4000};
__device__ __constant__ int   c_k[5]      = {1000, 1000, 1000, 1000, 720};
// k_hist slice mapping: lvl0 split 8-way, lvl1 2-way, lvl2..4 single
__device__ __constant__ int   c_slice_lvl[13] = {0,0,0,0,0,0,0,0,1,1,2,3,4};
__device__ __constant__ int   c_slice_id[13]  = {0,1,2,3,4,5,6,7,0,1,0,0,0};
__device__ __constant__ int   c_nslice[5]     = {8,2,1,1,1};

#define HBITS 13
#define HBINS (1 << HBITS)
#define HSHIFT (32 - HBITS)
#define BUF_CAP 8192

// Scratch (static device globals; k_sel re-zeros g_hist each call)
__device__ u32           g_hist[NB * 5 * HBINS];
__device__ u64           g_skey[NB * KTOT];   // per-level segments sorted by final-score key
__device__ float4        g_box[NB * KTOT];    // indexed by concat position r (pre-sort)
__device__ u8            g_lab[NB * KTOT];
__device__ u8            g_valid[NB * KTOT];
__device__ u8            g_slab[NB * KTOT];   // label | (valid<<7), sorted-row order
__device__ float         g_maxc1[NB];         // per-image max_coord + 1

struct Ptrs {
    const float* cls[5];
    const float* bb[5];
    const float* ct[5];
};

__device__ __forceinline__ u32 ordf(float f) {
    u32 u = __float_as_uint(f);
    return (u & 0x80000000u) ? ~u : (u | 0x80000000u);
}
__device__ __forceinline__ float unordf(u32 u) {
    return __uint_as_float((u & 0x80000000u) ? (u & 0x7FFFFFFFu) : ~u);
}

// XLA:CPU f32 exp (Eigen/Cephes pexp) with FMA contraction. PROTECT: bit-exact.
__device__ __forceinline__ float xla_cpu_expf(float x) {
    x = fminf(x,  88.3762626647950f);
    x = fmaxf(x, -88.3762626647949f);
    float fx = floorf(__fmaf_rn(x, 1.44269504088896341f, 0.5f));
    float r = __fmaf_rn(fx, -0.693359375f, x);
    r = __fmaf_rn(fx, 2.12194440e-4f, r);
    float r2 = __fmul_rn(r, r);
    float y = 1.9875691500e-4f;
    y = __fmaf_rn(y, r, 1.3981999507e-3f);
    y = __fmaf_rn(y, r, 8.3334519073e-3f);
    y = __fmaf_rn(y, r, 4.1665795894e-2f);
    y = __fmaf_rn(y, r, 1.6666665459e-1f);
    y = __fmaf_rn(y, r, 5.0000001201e-1f);
    y = __fmaf_rn(y, r2, r);
    y = __fadd_rn(y, 1.0f);
    int n = (int)fx;
    float s = __int_as_float((u32)(n + 127) << 23);
    return __fmul_rn(y, s);
}
__device__ __forceinline__ float sigm(float x) {
    return __fdiv_rn(1.0f, __fadd_rn(1.0f, xla_cpu_expf(-x)));
}

// IoU on offset boxes, exact reference float op order. PROTECT.
__device__ __forceinline__ bool suppresses(const float4 a, const float4 b) {
    float aa = __fmul_rn(__fsub_rn(a.z, a.x), __fsub_rn(a.w, a.y));
    float ab = __fmul_rn(__fsub_rn(b.z, b.x), __fsub_rn(b.w, b.y));
    float ltx = fmaxf(a.x, b.x), lty = fmaxf(a.y, b.y);
    float rbx = fminf(a.z, b.z), rby = fminf(a.w, b.w);
    float w = fmaxf(__fsub_rn(rbx, ltx), 0.0f), h = fmaxf(__fsub_rn(rby, lty), 0.0f);
    float inter = __fmul_rn(w, h);
    float uni = __fsub_rn(__fadd_rn(aa, ab), inter);
    float iou = (uni > 0.0f) ? __fdiv_rn(inter, uni) : 0.0f;
    return iou > IOUTHR;
}

// Merge-path pick: output element i of merge(A[0..n), B[0..m)); keys unique.
__device__ __forceinline__ u64 merge_pick(const u64* A, int n, const u64* Bb, int m, int i) {
    int lo = max(0, i - m), hi = min(i, n);
    while (lo < hi) {
        int mid = (lo + hi) >> 1;
        if (A[mid] < Bb[i - 1 - mid]) lo = mid + 1; else hi = mid;
    }
    int a = lo, bj = i - lo;
    if (a >= n) return Bb[bj];
    if (bj >= m) return A[a];
    u64 va = A[a], vb = Bb[bj];
    return va < vb ? va : vb;
}

// Warp-register bitonic sort of 32 u64 (ascending across lanes), no barriers.
__device__ __forceinline__ u64 warp_sort32(u64 v, int lane) {
    #pragma unroll
    for (int k2 = 2; k2 <= 32; k2 <<= 1) {
        #pragma unroll
        for (int j = k2 >> 1; j > 0; j >>= 1) {
            u64 o = __shfl_xor_sync(0xFFFFFFFFu, v, j);
            bool up = ((lane & k2) == 0);
            bool lower = ((lane & j) == 0);
            v = ((lower == up) ? (v < o ? v : o) : (v > o ? v : o));
        }
    }
    return v;
}

// Sort src[0..P) ascending (P power of 2 >= 1024, multiple of 32), aux = ping-pong.
__device__ u64* msort(u64* src, u64* aux, int P, int tid) {
    const int lane = tid & 31, wid = tid >> 5;
    for (int r = wid; r < (P >> 5); r += 32) {
        u64 v = src[r * 32 + lane];
        src[r * 32 + lane] = warp_sort32(v, lane);
    }
    __syncthreads();
    u64 *s = src, *d = aux;
    for (int L = 32; L < P; L <<= 1) {
        for (int e = tid; e < P; e += 1024) {
            int seg = (e / (L << 1)) * (L << 1);
            d[e] = merge_pick(s + seg, L, s + seg + L, L, e - seg);
        }
        __syncthreads();
        u64* t = s; s = d; d = t;
    }
    return s;
}

// ---------------------------------------------------------------------------
// Kernel 0: wide logit-ordinal histogram — privatized SMEM hist per slice
// block, flush nonzero bins to the global per-segment hist.
// ---------------------------------------------------------------------------
__global__ __launch_bounds__(512) void k_hist(Ptrs p) {
    const int sl = blockIdx.x;
    const int b = blockIdx.y;
    const int lvl = c_slice_lvl[sl];
    const int sid = c_slice_id[sl];
    const int A = c_A[lvl];
    const int N4 = A * 20;               // N/4
    const int ns = c_nslice[lvl];
    const int per = (N4 + ns - 1) / ns;
    const int i0 = sid * per;
    const int i1 = min(i0 + per, N4);

    __shared__ u32 h[HBINS];
    #pragma unroll
    for (int i = threadIdx.x; i < HBINS; i += 512) h[i] = 0;
    __syncthreads();

    const float4* cls4 = (const float4*)(p.cls[lvl] + (size_t)b * A * 80);
    for (int i = i0 + threadIdx.x; i < i1; i += 512) {
        float4 v = cls4[i];
        atomicAdd(&h[(~ordf(v.x)) >> HSHIFT], 1u);
        atomicAdd(&h[(~ordf(v.y)) >> HSHIFT], 1u);
        atomicAdd(&h[(~ordf(v.z)) >> HSHIFT], 1u);
        atomicAdd(&h[(~ordf(v.w)) >> HSHIFT], 1u);
    }
    __syncthreads();

    u32* gh = g_hist + (b * 5 + lvl) * HBINS;
    #pragma unroll
    for (int i = threadIdx.x; i < HBINS; i += 512) {
        u32 v = h[i];
        if (v) atomicAdd(&gh[i], v);
    }
}

// ---------------------------------------------------------------------------
// Kernel 1: per (lvl,b) block — bin scan -> boundary; float4 cull scan;
// exact score keys for survivors; msort; decode; per-level final-score sort.
// smem: buf u64[8192] | aux u64[8192] | fin u64[1024]
// ---------------------------------------------------------------------------
#define SEL_B_OFF 0
#define SEL_X_OFF 65536
#define SEL_F_OFF (65536 + 65536)
#define KSEL_SMEM (SEL_F_OFF + 8192)

__global__ __launch_bounds__(1024) void k_sel(Ptrs p) {
    const int lvl = blockIdx.x;
    const int b = blockIdx.y;
    const int tid = threadIdx.x;
    const int lane = tid & 31, wid = tid >> 5;

    const int w = c_w[lvl];
    const int A = c_A[lvl];
    const int N = A * 80;
    const int k = c_k[lvl];
    const int stride = c_stride[lvl];

    const float* cls = p.cls[lvl] + (size_t)b * N;
    u32* hist = g_hist + (b * 5 + lvl) * HBINS;

    extern __shared__ unsigned char smraw[];
    u64* buf = (u64*)(smraw + SEL_B_OFF);
    u64* aux = (u64*)(smraw + SEL_X_OFF);
    u64* fin = (u64*)(smraw + SEL_F_OFF);

    __shared__ u32 s_wsum[32];
    __shared__ int s_B;
    __shared__ u32 s_cnt;

    // scan bins (8/thread), block exclusive scan, find k-th crossing; re-zero
    const int b0 = tid * (HBINS / 1024);
    u32 bins[HBINS / 1024];
    u32 st = 0;
    #pragma unroll
    for (int j = 0; j < HBINS / 1024; j++) { bins[j] = hist[b0 + j]; st += bins[j]; }
    u32 incl = st;
    #pragma unroll
    for (int o = 1; o < 32; o <<= 1) {
        u32 v = __shfl_up_sync(0xFFFFFFFFu, incl, o);
        if (lane >= o) incl += v;
    }
    if (lane == 31) s_wsum[wid] = incl;
    __syncthreads();
    if (wid == 0) {
        u32 v = s_wsum[lane];
        #pragma unroll
        for (int o = 1; o < 32; o <<= 1) {
            u32 t2 = __shfl_up_sync(0xFFFFFFFFu, v, o);
            if (lane >= o) v += t2;
        }
        s_wsum[lane] = v;
    }
    __syncthreads();
    u32 myexcl = (wid ? s_wsum[wid - 1] : 0u) + (incl - st);
    if (myexcl < (u32)k && myexcl + st >= (u32)k) {
        u32 cum = myexcl;
        #pragma unroll
        for (int j = 0; j < HBINS / 1024; j++) {
            if (cum + bins[j] >= (u32)k) { s_B = b0 + j; break; }
            cum += bins[j];
        }
    }
    // re-zero global hist for next graph replay
    #pragma unroll
    for (int j = 0; j < HBINS / 1024; j++) hist[b0 + j] = 0;
    if (tid == 0) s_cnt = 0;
    __syncthreads();
    const u32 Bg = (u32)s_B + 1;   // guard bin included (covers all score ties)

    // gather: float4 scan, cheap logit-prefix cull; exact score key for survivors
    const float4* cls4 = (const float4*)cls;
    const int N4 = N >> 2;
    for (int i = tid; i < N4; i += 1024) {
        float4 v = cls4[i];
        #pragma unroll
        for (int cc = 0; cc < 4; cc++) {
            float x = (cc == 0) ? v.x : (cc == 1) ? v.y : (cc == 2) ? v.z : v.w;
            u32 pl = (~ordf(x)) >> HSHIFT;
            if (pl <= Bg) {
                float s = sigm(x);
                float mv = (s > THR) ? s : -1.0f;
                int ie = i * 4 + cc;         // memory index = c*A + anchor
                int c = ie / A;
                int anchor = ie - c * A;
                u64 key = ((u64)(~ordf(mv)) << 32) | (u32)(anchor * 80 + c);
                u32 pos = atomicAdd(&s_cnt, 1u);
                if (pos < BUF_CAP) buf[pos] = key;
            }
        }
    }
    __syncthreads();
    int nG = (int)min(s_cnt, (u32)BUF_CAP);

    int P = 1024;
    while (P < nG) P <<= 1;
    for (int e = tid; e < P; e += 1024) if (e >= nG) buf[e] = ~0ull;
    __syncthreads();
    u64* res = msort(buf, aux, P, tid);

    // decode + emit top-k (exact float ops — PROTECT); build final-score keys
    u64 fkey = ~0ull;
    if (tid < k) {
        u64 key = res[tid];
        int e = (int)(key & 0xFFFFFFFFull);
        float mv = unordf(~(u32)(key >> 32));
        int anchor = e / 80;
        int lab = e - anchor * 80;
        int y = anchor / w;
        int x = anchor - y * w;
        const float* bb = p.bb[lvl];
        const float* ct = p.ct[lvl];
        float sf = sigm(ct[(size_t)b * A + anchor]);
        float dl = bb[((size_t)b * 4 + 0) * A + anchor];
        float dt = bb[((size_t)b * 4 + 1) * A + anchor];
        float dr = bb[((size_t)b * 4 + 2) * A + anchor];
        float db = bb[((size_t)b * 4 + 3) * A + anchor];
        float px = __fmul_rn(__fadd_rn((float)x, 0.5f), (float)stride);
        float py = __fmul_rn(__fadd_rn((float)y, 0.5f), (float)stride);
        float4 bx;
        bx.x = fminf(fmaxf(__fsub_rn(px, dl), 0.0f), IMGSZ);
        bx.y = fminf(fmaxf(__fsub_rn(py, dt), 0.0f), IMGSZ);
        bx.z = fminf(fmaxf(__fadd_rn(px, dr), 0.0f), IMGSZ);
        bx.w = fminf(fmaxf(__fadd_rn(py, db), 0.0f), IMGSZ);
        bool valid = mv > THR;
        float score = valid ? __fmul_rn(mv, sf) : -1.0f;
        int r = c_outoff[lvl] + tid;    // reference concat position
        int g = b * KTOT + r;
        g_box[g] = bx;
        g_lab[g] = (u8)lab;
        g_valid[g] = valid ? 1 : 0;
        fkey = ((u64)(~ordf(score)) << 32) | (u32)r;
    }
    fin[tid] = fkey;
    __syncthreads();

    // per-level sort by final-score key (unique keys)
    u64* res2 = msort(fin, aux, 1024, tid);
    if (tid < k) g_skey[b * KTOT + c_outoff[lvl] + tid] = res2[tid];
}

// ---------------------------------------------------------------------------
// Kernel 2: per image — max-coord, 3-round merge-path merge of 5 sorted
// segments (keys unique => identical permutation to full sort), write
// dets/labels + label|valid bytes (sorted-row order) + maxc1.
// ---------------------------------------------------------------------------
#define KSORT_SMEM (KTOT * 8 * 2)

__global__ __launch_bounds__(1024) void k_sort(float* __restrict__ out) {
    const int b = blockIdx.x;
    const int tid = threadIdx.x;
    const int K = KTOT;
    const int lane = tid & 31, wid = tid >> 5;

    extern __shared__ unsigned char smraw[];
    u64* bufA = (u64*)smraw;
    u64* bufB = (u64*)(smraw + KTOT * 8);

    __shared__ float s_red[32];

    const float* bf = (const float*)(g_box + b * K);
    float m = -3.0e38f;
    for (int e = tid; e < K * 4; e += 1024) m = fmaxf(m, bf[e]);
    #pragma unroll
    for (int o = 16; o; o >>= 1) m = fmaxf(m, __shfl_xor_sync(0xFFFFFFFFu, m, o));
    if (lane == 0) s_red[wid] = m;
    __syncthreads();
    if (tid == 0) {
        float v = s_red[0];
        for (int i = 1; i < 32; i++) v = fmaxf(v, s_red[i]);
        g_maxc1[b] = __fadd_rn(v, 1.0f);
    }

    for (int e = tid; e < K; e += 1024) bufA[e] = g_skey[b * K + e];
    __syncthreads();

    #pragma unroll
    for (int mr = 0; mr < 5; mr++) {
        int e = tid + mr * 1024;
        if (e < K) {
            u64 v;
            if (e < 2000)      v = merge_pick(bufA,        1000, bufA + 1000, 1000, e);
            else if (e < 4000) v = merge_pick(bufA + 2000, 1000, bufA + 3000, 1000, e - 2000);
            else               v = bufA[e];
            bufB[e] = v;
        }
    }
    __syncthreads();

    #pragma unroll
    for (int mr = 0; mr < 5; mr++) {
        int e = tid + mr * 1024;
        if (e < K) {
            u64 v;
            if (e < 4000) v = merge_pick(bufB, 2000, bufB + 2000, 2000, e);
            else          v = bufB[e];
            bufA[e] = v;
        }
    }
    __syncthreads();

    #pragma unroll
    for (int mr = 0; mr < 5; mr++) {
        int e = tid + mr * 1024;
        if (e < K) bufB[e] = merge_pick(bufA, 4000, bufA + 4000, 720, e);
    }
    __syncthreads();

    float* outD = out + (size_t)b * K * 5;
    float* outL = out + (size_t)NB * K * 5 + (size_t)b * K;

    #pragma unroll
    for (int mr = 0; mr < 5; mr++) {
        int r = tid + mr * 1024;
        if (r < K) {
            u64 key = bufB[r];
            int src = (int)(key & 0xFFFFFFFFull);
            float sc = unordf(~(u32)(key >> 32));
            float4 bx = g_box[b * K + src];
            int lab = g_lab[b * K + src];
            u8 valid = g_valid[b * K + src];
            outD[r * 5 + 0] = bx.x;
            outD[r * 5 + 1] = bx.y;
            outD[r * 5 + 2] = bx.z;
            outD[r * 5 + 3] = bx.w;
            outD[r * 5 + 4] = sc;
            outL[r] = (float)lab;
            g_slab[b * K + r] = (u8)(lab | (valid << 7));
        }
    }
}

// ---------------------------------------------------------------------------
// Kernel 3: one warp per (class, image) — ballot-compact class rows in sorted
// order, rebuild offset boxes from dets + maxc1 (identical __f*_rn ops),
// greedy NMS (exact: cross-class IoU == 0), write keep for class rows.
// CAP=1280 (binomial(4720,1/80): mean 59, sd 7.6 — overflow impossible here).
// ---------------------------------------------------------------------------
#define NMS_CAP 1280
#define KNMS2_SMEM (NMS_CAP * 2 + NMS_CAP + NMS_CAP * 16 + 16)

__global__ __launch_bounds__(32) void k_nms2(float* __restrict__ out) {
    const int c = blockIdx.x;
    const int b = blockIdx.y;
    const int lane = threadIdx.x;
    const int K = KTOT;

    extern __shared__ unsigned char smraw[];
    u16* s_idx = (u16*)smraw;
    u8* s_alive = smraw + NMS_CAP * 2;
    float4* s_box = (float4*)(smraw + ((NMS_CAP * 3 + 15) & ~15));

    const u8* slab = g_slab + b * K;
    const float maxc1 = g_maxc1[b];
    const float off = __fmul_rn((float)c, maxc1);

    // ballot compaction in sorted-row order
    int cnt = 0;
    for (int it = 0; it < (K + 31) / 32; it++) {
        int r = it * 32 + lane;
        u8 byte = (r < K) ? slab[r] : 0xFF;
        bool match = (r < K) && ((byte & 0x7F) == c);
        u32 mask = __ballot_sync(0xFFFFFFFFu, match);
        if (match) {
            int pos = cnt + __popc(mask & ((1u << lane) - 1u));
            if (pos < NMS_CAP) {
                s_idx[pos] = (u16)r;
                s_alive[pos] = byte >> 7;
            }
        }
        cnt += __popc(mask);
    }
    if (cnt > NMS_CAP) cnt = NMS_CAP;
    __syncwarp();

    // rebuild offset boxes from dets rows (same ops as reference: box + lab*maxc1)
    const float* outD = out + (size_t)b * K * 5;
    for (int i = lane; i < cnt; i += 32) {
        int r = s_idx[i];
        float4 ob;
        ob.x = __fadd_rn(outD[r * 5 + 0], off);
        ob.y = __fadd_rn(outD[r * 5 + 1], off);
        ob.z = __fadd_rn(outD[r * 5 + 2], off);
        ob.w = __fadd_rn(outD[r * 5 + 3], off);
        s_box[i] = ob;
    }
    __syncwarp();

    // greedy (sequential in sorted order, lane-parallel suppression)
    for (int i = 0; i < cnt; i++) {
        if (s_alive[i]) {
            float4 bi = s_box[i];
            for (int j = i + 1 + lane; j < cnt; j += 32) {
                if (s_alive[j] && suppresses(bi, s_box[j])) s_alive[j] = 0;
            }
        }
        __syncwarp();
    }

    float* outKp = out + (size_t)NB * K * 5 + (size_t)NB * K + (size_t)b * K;
    for (int i = lane; i < cnt; i += 32)
        outKp[s_idx[i]] = s_alive[i] ? 1.0f : 0.0f;
}

// ---------------------------------------------------------------------------
extern "C" void kernel_launch(void* const* d_in, const int* in_sizes, int n_in,
                              void* d_out, int out_size) {
    (void)n_in; (void)out_size;
    Ptrs p;
    bool interleaved = (in_sizes[1] == 25600);
    for (int i = 0; i < 5; i++) {
        if (interleaved) {
            p.cls[i] = (const float*)d_in[3 * i + 0];
            p.bb[i]  = (const float*)d_in[3 * i + 1];
            p.ct[i]  = (const float*)d_in[3 * i + 2];
        } else {
            p.cls[i] = (const float*)d_in[i];
            p.bb[i]  = (const float*)d_in[5 + i];
            p.ct[i]  = (const float*)d_in[10 + i];
        }
    }
    k_hist<<<dim3(13, NB), 512>>>(p);
    cudaFuncSetAttribute(k_sel, cudaFuncAttributeMaxDynamicSharedMemorySize, KSEL_SMEM);
    k_sel<<<dim3(5, NB), 1024, KSEL_SMEM>>>(p);
    cudaFuncSetAttribute(k_sort, cudaFuncAttributeMaxDynamicSharedMemorySize, KSORT_SMEM);
    k_sort<<<NB, 1024, KSORT_SMEM>>>((float*)d_out);
    cudaFuncSetAttribute(k_nms2, cudaFuncAttributeMaxDynamicSharedMemorySize, KNMS2_SMEM);
    k_nms2<<<dim3(NCLS, NB), 32, KNMS2_SMEM>>>((float*)d_out);
}